// round 11
// baseline (speedup 1.0000x reference)
#include <cuda_runtime.h>
#include <cuda_bf16.h>
#include <math.h>
#include <stdint.h>

#define BATCH 64
#define KCODES 512
#define DDIM 64

__device__ float d_h1 [BATCH * 64 * 64 * 64];
__device__ float d_a  [BATCH * 128 * 32 * 32];
__device__ float d_b  [BATCH * 128 * 32 * 32];
__device__ float d_mid[BATCH * 64 * 32 * 32];
__device__ float d_ze [BATCH * 64 * 32 * 32];
__device__ float d_zq [BATCH * 64 * 32 * 32];
__device__ float d_enorm [KCODES];
__device__ float d_counts[KCODES];
__device__ float d_sqsum[1];
__device__ __nv_bfloat16 d_whi[1 << 20];
__device__ __nv_bfloat16 d_wlo[1 << 20];

__device__ __forceinline__ uint32_t smem_u32(const void* p) {
    uint32_t a;
    asm("{ .reg .u64 t; cvta.to.shared.u64 t, %1; cvt.u32.u64 %0, t; }" : "=r"(a) : "l"(p));
    return a;
}
__device__ __forceinline__ void mma_bf16(float* c, const uint32_t* a, const uint32_t* b) {
    asm volatile(
        "mma.sync.aligned.m16n8k16.row.col.f32.bf16.bf16.f32 "
        "{%0,%1,%2,%3}, {%4,%5,%6,%7}, {%8,%9}, {%0,%1,%2,%3};"
        : "+f"(c[0]), "+f"(c[1]), "+f"(c[2]), "+f"(c[3])
        : "r"(a[0]), "r"(a[1]), "r"(a[2]), "r"(a[3]), "r"(b[0]), "r"(b[1]));
}
__device__ __forceinline__ void ldm4(uint32_t* a, uint32_t addr) {
    asm volatile("ldmatrix.sync.aligned.m8n8.x4.shared.b16 {%0,%1,%2,%3}, [%4];"
                 : "=r"(a[0]), "=r"(a[1]), "=r"(a[2]), "=r"(a[3]) : "r"(addr));
}
__device__ __forceinline__ void split2(float f0, float f1, uint32_t& hp, uint32_t& lp) {
    asm("cvt.rn.bf16x2.f32 %0, %1, %2;" : "=r"(hp) : "f"(f1), "f"(f0));
    float h0 = __uint_as_float(hp << 16);
    float h1 = __uint_as_float(hp & 0xffff0000u);
    asm("cvt.rn.bf16x2.f32 %0, %1, %2;" : "=r"(lp) : "f"(f1 - h1), "f"(f0 - h0));
}

// window: [6 rows][36 cols][64 ci] bf16, 128B/(row,col), granule(16B) XOR-swizzled by col&7
static constexpr int WBYTES = 6 * 36 * 128;   // 27648
static constexpr int MC_SMEM = 2 * WBYTES;    // 55296

template<int CIN, bool RELU_IN>
__device__ __forceinline__ void stage_window(const float* __restrict__ in,
                                             int n, int kc, int by,
                                             int wid, int lane, char* smem)
{
    if (wid >= 6) return;
    const int y = wid, cp = lane;
    const int y_in = by * 4 + y - 1;
    const bool yok = (y_in >= 0) && (y_in < 32);
    const uint32_t wordoff = (uint32_t)((cp & 3) << 2);
    const uint32_t g0 = (uint32_t)(cp >> 2);

    auto st = [&](int xc, uint32_t hp, uint32_t lp) {
        uint32_t off = (uint32_t)((y * 36 + xc) << 7) + (((g0 ^ (uint32_t)(xc & 7)) << 4)) + wordoff;
        *(uint32_t*)(smem + off) = hp;
        *(uint32_t*)(smem + WBYTES + off) = lp;
    };
    st(0, 0u, 0u); st(33, 0u, 0u); st(34, 0u, 0u); st(35, 0u, 0u);
    if (yok) {
        const float* p0 = in + ((size_t)n * CIN + kc * 64 + 2 * cp) * 1024 + y_in * 32;
#pragma unroll
        for (int j = 0; j < 8; j++) {
            float4 a4 = *(const float4*)(p0 + 4 * j);
            float4 b4 = *(const float4*)(p0 + 1024 + 4 * j);
            if (RELU_IN) {
                a4.x = fmaxf(a4.x, 0.f); a4.y = fmaxf(a4.y, 0.f);
                a4.z = fmaxf(a4.z, 0.f); a4.w = fmaxf(a4.w, 0.f);
                b4.x = fmaxf(b4.x, 0.f); b4.y = fmaxf(b4.y, 0.f);
                b4.z = fmaxf(b4.z, 0.f); b4.w = fmaxf(b4.w, 0.f);
            }
            float fa[4] = {a4.x, a4.y, a4.z, a4.w};
            float fb[4] = {b4.x, b4.y, b4.z, b4.w};
#pragma unroll
            for (int e = 0; e < 4; e++) {
                uint32_t hp, lp;
                split2(fa[e], fb[e], hp, lp);
                st(1 + 4 * j + e, hp, lp);
            }
        }
    } else {
#pragma unroll
        for (int xc = 1; xc <= 32; xc++) st(xc, 0u, 0u);
    }
}

__device__ __forceinline__ void stage_window_s2(const float* __restrict__ in,
                                                int n, int by, int sy, int sx,
                                                int wid, int lane, char* smem)
{
    if (wid >= 6) return;
    const int y = wid, cp = lane;
    const int r_w = by * 4 + y - 1;
    const bool yok = (r_w >= 0) && (r_w < 32);
    const int iy = 2 * r_w + sy;
    const uint32_t wordoff = (uint32_t)((cp & 3) << 2);
    const uint32_t g0 = (uint32_t)(cp >> 2);

    auto st = [&](int xc, uint32_t hp, uint32_t lp) {
        uint32_t off = (uint32_t)((y * 36 + xc) << 7) + (((g0 ^ (uint32_t)(xc & 7)) << 4)) + wordoff;
        *(uint32_t*)(smem + off) = hp;
        *(uint32_t*)(smem + WBYTES + off) = lp;
    };
    st(0, 0u, 0u); st(33, 0u, 0u); st(34, 0u, 0u); st(35, 0u, 0u);
    if (yok) {
        const float* p0 = in + ((size_t)n * 64 + 2 * cp) * 4096 + iy * 64;
#pragma unroll
        for (int j = 0; j < 16; j++) {
            float4 a4 = *(const float4*)(p0 + 4 * j);
            float4 b4 = *(const float4*)(p0 + 4096 + 4 * j);
            float fa0 = sx ? a4.y : a4.x, fa1 = sx ? a4.w : a4.z;
            float fb0 = sx ? b4.y : b4.x, fb1 = sx ? b4.w : b4.z;
            uint32_t hp, lp;
            split2(fa0, fb0, hp, lp); st(1 + 2 * j, hp, lp);
            split2(fa1, fb1, hp, lp); st(2 + 2 * j, hp, lp);
        }
    } else {
#pragma unroll
        for (int xc = 1; xc <= 32; xc++) st(xc, 0u, 0u);
    }
}

// ---------------- merged weight prep ----------------
struct WPrepArgs {
    const float* s[12];
    const float* tc1;
    const float* c2;
};
__constant__ struct { int off, size, cout, cin, kk; } c_wseg[12];

__global__ void wprep_all_k(WPrepArgs a, __nv_bfloat16* __restrict__ hi, __nv_bfloat16* __restrict__ lo)
{
    const int O_TC1 = 704512, O_C2 = 835584, TOT = 966656;
    int i = blockIdx.x * 256 + threadIdx.x;
    if (i >= TOT) return;
    float f;
    if (i >= O_C2) {
        int j = i - O_C2;
        int ci = j & 63, co = (j >> 6) & 127, g = j >> 13;
        int sg = g >> 2, jt = g & 3;
        int sy = sg >> 1, sx = sg & 1, jy = jt >> 1, jx = jt & 1;
        int ky = 2 * jy + (1 - sy), kx = 2 * jx + (1 - sx);
        f = a.c2[((co * 64 + ci) * 4 + ky) * 4 + kx];
    } else if (i >= O_TC1) {
        int j = i - O_TC1;
        int ci = j & 127, co = (j >> 7) & 63, g = j >> 13;
        int pz = g >> 2, jt = g & 3;
        int py = pz >> 1, px = pz & 1, jy = jt >> 1, jx = jt & 1;
        int ky = (1 - py) + 2 * jy, kx = (1 - px) + 2 * jx;
        f = a.tc1[((ci * 64 + co) * 4 + ky) * 4 + kx];
    } else {
        int sidx = 0;
#pragma unroll
        for (int q = 1; q < 12; q++)
            if (i >= c_wseg[q].off) sidx = q;
        int j = i - c_wseg[sidx].off;
        int cin = c_wseg[sidx].cin, cout = c_wseg[sidx].cout, kk = c_wseg[sidx].kk;
        int ci = j % cin, co = (j / cin) % cout, t = j / (cin * cout);
        f = a.s[sidx][((size_t)co * cin + ci) * kk + t];
    }
    __nv_bfloat16 h = __float2bfloat16(f);
    hi[i] = h;
    lo[i] = __float2bfloat16(f - __bfloat162float(h));
}

// ---------------- direct-ldmatrix mma conv, warp tile = MT m-tiles x 32 co ----------------
template<int CIN, int COUT, int KS, bool RELU_IN, bool RELU_OUT, bool HAS_BIAS, bool ADD_RES>
__global__ void __launch_bounds__(256) mconv2_k(
    const float* __restrict__ in,
    const __nv_bfloat16* __restrict__ whi, const __nv_bfloat16* __restrict__ wlo,
    const float* __restrict__ bias, const float* __restrict__ res,
    float* __restrict__ out)
{
    constexpr int KCH = CIN / 64;
    constexpr int CW = COUT / 32;     // co-groups
    constexpr int MT = CW;            // m-tiles per warp (8/MW, MW=8/CW)
    constexpr int NF = 4;
    extern __shared__ char smem[];
    const uint32_t sH = smem_u32(smem), sL = sH + WBYTES;

    const int tid = threadIdx.x, wid = tid >> 5, lane = tid & 31;
    const int by = blockIdx.x, n = blockIdx.z;
    const int mg = wid / CW, cg = wid % CW;
    const int cobase = cg * 32;
    const int rowidx = ((lane >> 3) & 1) * 8 + (lane & 7);
    const int khalf = lane >> 4;

    float acc[MT][NF][4];
#pragma unroll
    for (int m = 0; m < MT; m++)
#pragma unroll
        for (int f = 0; f < NF; f++)
#pragma unroll
            for (int k = 0; k < 4; k++) acc[m][f][k] = 0.f;

    for (int kc = 0; kc < KCH; kc++) {
        if (kc) __syncthreads();
        stage_window<CIN, RELU_IN>(in, n, kc, by, wid, lane, smem);
        __syncthreads();

        for (int t = 0; t < KS * KS; t++) {
            const int dy = (KS == 1) ? 1 : t / KS;
            const int dx = (KS == 1) ? 1 : t % KS;
            const int cx = rowidx + dx;
            const uint32_t cx7 = (uint32_t)(cx & 7);
#pragma unroll
            for (int k16 = 0; k16 < 4; k16++) {
                const int kb = kc * 64 + k16 * 16 + (lane & 3) * 2;
                uint32_t bh[NF][2], bl[NF][2];
#pragma unroll
                for (int f = 0; f < NF; f++) {
                    int co = cobase + f * 8 + (lane >> 2);
                    size_t base = ((size_t)t * COUT + co) * CIN + kb;
                    bh[f][0] = *(const uint32_t*)(whi + base);
                    bh[f][1] = *(const uint32_t*)(whi + base + 8);
                    bl[f][0] = *(const uint32_t*)(wlo + base);
                    bl[f][1] = *(const uint32_t*)(wlo + base + 8);
                }
                const uint32_t gsw = (((uint32_t)(k16 * 2 + khalf) ^ cx7) << 4);
#pragma unroll
                for (int m = 0; m < MT; m++) {
                    const int mm = mg * MT + m;
                    uint32_t off = (uint32_t)((((mm >> 1) + dy) * 36 + (mm & 1) * 16 + cx) << 7) + gsw;
                    uint32_t ah[4], al[4];
                    ldm4(ah, sH + off);
                    ldm4(al, sL + off);
#pragma unroll
                    for (int f = 0; f < NF; f++) {
                        mma_bf16(acc[m][f], ah, bh[f]);
                        mma_bf16(acc[m][f], ah, bl[f]);
                        mma_bf16(acc[m][f], al, bh[f]);
                    }
                }
            }
        }
    }

    const int r0 = lane >> 2, c0 = (lane & 3) * 2;
#pragma unroll
    for (int m = 0; m < MT; m++)
#pragma unroll
        for (int f = 0; f < NF; f++) {
            const int mm = mg * MT + m;
            int co = cobase + f * 8 + c0;
            int gp = by * 128 + mm * 16 + r0;
            float b0v = HAS_BIAS ? bias[co] : 0.f;
            float b1v = HAS_BIAS ? bias[co + 1] : 0.f;
            float v00 = acc[m][f][0] + b0v, v01 = acc[m][f][1] + b1v;
            float v10 = acc[m][f][2] + b0v, v11 = acc[m][f][3] + b1v;
            size_t o0 = ((size_t)n * COUT + co) * 1024 + gp;
            size_t o1 = ((size_t)n * COUT + co + 1) * 1024 + gp;
            if (ADD_RES) {
                v00 += res[o0]; v01 += res[o1];
                v10 += res[o0 + 8]; v11 += res[o1 + 8];
            }
            if (RELU_OUT) {
                v00 = fmaxf(v00, 0.f); v01 = fmaxf(v01, 0.f);
                v10 = fmaxf(v10, 0.f); v11 = fmaxf(v11, 0.f);
            }
            out[o0] = v00; out[o1] = v01;
            out[o0 + 8] = v10; out[o1 + 8] = v11;
        }
}

// ---------------- conv2 as tensor: 4 parity subgrids x 2x2 taps (MW=2 split) ----------------
__global__ void __launch_bounds__(256) c2m_k(
    const float* __restrict__ in,
    const __nv_bfloat16* __restrict__ whi, const __nv_bfloat16* __restrict__ wlo,
    const float* __restrict__ bias, float* __restrict__ out)
{
    constexpr int COUT = 128, CW = 4, MT = 4, NF = 4;
    extern __shared__ char smem[];
    const uint32_t sH = smem_u32(smem), sL = sH + WBYTES;

    const int tid = threadIdx.x, wid = tid >> 5, lane = tid & 31;
    const int by = blockIdx.x, n = blockIdx.z;
    const int mg = wid / CW, cg = wid % CW;
    const int cobase = cg * 32;
    const int rowidx = ((lane >> 3) & 1) * 8 + (lane & 7);
    const int khalf = lane >> 4;

    float acc[MT][NF][4];
#pragma unroll
    for (int m = 0; m < MT; m++)
#pragma unroll
        for (int f = 0; f < NF; f++)
#pragma unroll
            for (int k = 0; k < 4; k++) acc[m][f][k] = 0.f;

    for (int sg = 0; sg < 4; sg++) {
        const int sy = sg >> 1, sx = sg & 1;
        if (sg) __syncthreads();
        stage_window_s2(in, n, by, sy, sx, wid, lane, smem);
        __syncthreads();

        for (int jt = 0; jt < 4; jt++) {
            const int jy = jt >> 1, jx = jt & 1;
            const int dy = jy + 1 - sy;
            const int dx = jx + 1 - sx;
            const int cx = rowidx + dx;
            const uint32_t cx7 = (uint32_t)(cx & 7);
            const int g = sg * 4 + jt;
#pragma unroll
            for (int k16 = 0; k16 < 4; k16++) {
                const int kb = k16 * 16 + (lane & 3) * 2;
                uint32_t bh[NF][2], bl[NF][2];
#pragma unroll
                for (int f = 0; f < NF; f++) {
                    int co = cobase + f * 8 + (lane >> 2);
                    size_t base = ((size_t)g * COUT + co) * 64 + kb;
                    bh[f][0] = *(const uint32_t*)(whi + base);
                    bh[f][1] = *(const uint32_t*)(whi + base + 8);
                    bl[f][0] = *(const uint32_t*)(wlo + base);
                    bl[f][1] = *(const uint32_t*)(wlo + base + 8);
                }
                const uint32_t gsw = (((uint32_t)(k16 * 2 + khalf) ^ cx7) << 4);
#pragma unroll
                for (int m = 0; m < MT; m++) {
                    const int mm = mg * MT + m;
                    uint32_t off = (uint32_t)((((mm >> 1) + dy) * 36 + (mm & 1) * 16 + cx) << 7) + gsw;
                    uint32_t ah[4], al[4];
                    ldm4(ah, sH + off);
                    ldm4(al, sL + off);
#pragma unroll
                    for (int f = 0; f < NF; f++) {
                        mma_bf16(acc[m][f], ah, bh[f]);
                        mma_bf16(acc[m][f], ah, bl[f]);
                        mma_bf16(acc[m][f], al, bh[f]);
                    }
                }
            }
        }
    }

    const int r0 = lane >> 2, c0 = (lane & 3) * 2;
#pragma unroll
    for (int m = 0; m < MT; m++)
#pragma unroll
        for (int f = 0; f < NF; f++) {
            const int mm = mg * MT + m;
            int co = cobase + f * 8 + c0;
            int gp = by * 128 + mm * 16 + r0;
            float b0v = bias[co], b1v = bias[co + 1];
            float v00 = fmaxf(acc[m][f][0] + b0v, 0.f);
            float v01 = fmaxf(acc[m][f][1] + b1v, 0.f);
            float v10 = fmaxf(acc[m][f][2] + b0v, 0.f);
            float v11 = fmaxf(acc[m][f][3] + b1v, 0.f);
            size_t o0 = ((size_t)n * COUT + co) * 1024 + gp;
            size_t o1 = ((size_t)n * COUT + co + 1) * 1024 + gp;
            out[o0] = v00; out[o1] = v01;
            out[o0 + 8] = v10; out[o1 + 8] = v11;
        }
}

// ---------------- tc1 as tensor convT (MW=4 split) ----------------
__global__ void __launch_bounds__(256) tmct_k(
    const float* __restrict__ in,
    const __nv_bfloat16* __restrict__ whi, const __nv_bfloat16* __restrict__ wlo,
    const float* __restrict__ bias, float* __restrict__ out)
{
    constexpr int CIN = 128, COUT = 64, CW = 2, MT = 2, NF = 4;
    extern __shared__ char smem[];
    const uint32_t sH = smem_u32(smem), sL = sH + WBYTES;

    const int tid = threadIdx.x, wid = tid >> 5, lane = tid & 31;
    const int by = blockIdx.x, pz = blockIdx.y, n = blockIdx.z;
    const int py = pz >> 1, px = pz & 1;
    const int mg = wid / CW, cg = wid % CW;
    const int cobase = cg * 32;
    const int rowidx = ((lane >> 3) & 1) * 8 + (lane & 7);
    const int khalf = lane >> 4;

    float acc[MT][NF][4];
#pragma unroll
    for (int m = 0; m < MT; m++)
#pragma unroll
        for (int f = 0; f < NF; f++)
#pragma unroll
            for (int k = 0; k < 4; k++) acc[m][f][k] = 0.f;

    for (int kc = 0; kc < 2; kc++) {
        if (kc) __syncthreads();
        stage_window<CIN, true>(in, n, kc, by, wid, lane, smem);
        __syncthreads();

        for (int jt = 0; jt < 4; jt++) {
            const int jy = jt >> 1, jx = jt & 1;
            const int dy = 1 - jy + py;
            const int dx = 1 - jx + px;
            const int cx = rowidx + dx;
            const uint32_t cx7 = (uint32_t)(cx & 7);
            const int g = pz * 4 + jt;
#pragma unroll
            for (int k16 = 0; k16 < 4; k16++) {
                const int kb = kc * 64 + k16 * 16 + (lane & 3) * 2;
                uint32_t bh[NF][2], bl[NF][2];
#pragma unroll
                for (int f = 0; f < NF; f++) {
                    int co = cobase + f * 8 + (lane >> 2);
                    size_t base = ((size_t)g * COUT + co) * CIN + kb;
                    bh[f][0] = *(const uint32_t*)(whi + base);
                    bh[f][1] = *(const uint32_t*)(whi + base + 8);
                    bl[f][0] = *(const uint32_t*)(wlo + base);
                    bl[f][1] = *(const uint32_t*)(wlo + base + 8);
                }
                const uint32_t gsw = (((uint32_t)(k16 * 2 + khalf) ^ cx7) << 4);
#pragma unroll
                for (int m = 0; m < MT; m++) {
                    const int mm = mg * MT + m;
                    uint32_t off = (uint32_t)((((mm >> 1) + dy) * 36 + (mm & 1) * 16 + cx) << 7) + gsw;
                    uint32_t ah[4], al[4];
                    ldm4(ah, sH + off);
                    ldm4(al, sL + off);
#pragma unroll
                    for (int f = 0; f < NF; f++) {
                        mma_bf16(acc[m][f], ah, bh[f]);
                        mma_bf16(acc[m][f], ah, bl[f]);
                        mma_bf16(acc[m][f], al, bh[f]);
                    }
                }
            }
        }
    }

    const int r0 = lane >> 2, c0 = (lane & 3) * 2;
#pragma unroll
    for (int m = 0; m < MT; m++)
#pragma unroll
        for (int f = 0; f < NF; f++) {
            const int mm = mg * MT + m;
            int p = mm * 16 + r0;
            int co = cobase + f * 8 + c0;
            int ga = by * 4 + (p >> 5), gb = p & 31;
            int oy = 2 * ga + py, ox = 2 * gb + px;
            float b0v = bias[co], b1v = bias[co + 1];
            float v00 = fmaxf(acc[m][f][0] + b0v, 0.f);
            float v01 = fmaxf(acc[m][f][1] + b1v, 0.f);
            float v10 = fmaxf(acc[m][f][2] + b0v, 0.f);
            float v11 = fmaxf(acc[m][f][3] + b1v, 0.f);
            size_t o00 = (((size_t)n * 64 + co) * 64 + oy) * 64 + ox;
            out[o00] = v00; out[o00 + 4096] = v01;
            out[o00 + 16] = v10; out[o00 + 4096 + 16] = v11;
        }
}

// ---------------- f32x2 helpers ----------------
__device__ __forceinline__ unsigned long long pk2(float a, float b) {
    unsigned long long r;
    asm("mov.b64 %0, {%1, %2};" : "=l"(r) : "f"(a), "f"(b));
    return r;
}
__device__ __forceinline__ void fma2(unsigned long long& d, unsigned long long a, unsigned long long b) {
    asm("fma.rn.f32x2 %0, %1, %2, %0;" : "+l"(d) : "l"(a), "l"(b));
}
__device__ __forceinline__ float2 upk2(unsigned long long a) {
    float2 f;
    asm("mov.b64 {%0, %1}, %2;" : "=f"(f.x), "=f"(f.y) : "l"(a));
    return f;
}

// ---------------- generic direct conv (conv1 only) ----------------
template<int CIN, int COUT, int KS, int STR, int PAD, int IH, int IW, int CO_BLK, int PX,
         bool RELU_OUT>
__global__ void __launch_bounds__(256) conv_k(
    const float* __restrict__ in, const float* __restrict__ w,
    const float* __restrict__ bias, float* __restrict__ out)
{
    constexpr int OH = (IH + 2 * PAD - KS) / STR + 1;
    constexpr int OW = (IW + 2 * PAD - KS) / STR + 1;
    constexpr int KK = KS * KS;
    constexpr int COLS = STR * (PX - 1) + KS;
    extern __shared__ float sw[];

    const int n = blockIdx.z, co0 = blockIdx.y * CO_BLK, tid = threadIdx.x;
    for (int i = tid; i < CIN * KK * CO_BLK; i += blockDim.x) {
        int co = i % CO_BLK, t = (i / CO_BLK) % KK, ci = i / (CO_BLK * KK);
        sw[i] = w[((size_t)(co0 + co) * CIN + ci) * KK + t];
    }
    __syncthreads();

    int p0 = (blockIdx.x * blockDim.x + tid) * PX;
    if (p0 >= OH * OW) return;
    int oy = p0 / OW, ox0 = p0 % OW;
    int iy0 = oy * STR - PAD, ix0 = ox0 * STR - PAD;

    bool rok[KS]; int roff[KS];
#pragma unroll
    for (int ky = 0; ky < KS; ky++) {
        int y = iy0 + ky; rok[ky] = (y >= 0) && (y < IH); roff[ky] = y * IW;
    }
    bool cok[COLS]; int coff[COLS];
#pragma unroll
    for (int cx = 0; cx < COLS; cx++) {
        int x = ix0 + cx; cok[cx] = (x >= 0) && (x < IW); coff[cx] = x;
    }

    unsigned long long acc[PX][CO_BLK / 2];
#pragma unroll
    for (int px = 0; px < PX; px++)
#pragma unroll
        for (int j = 0; j < CO_BLK / 2; j++) acc[px][j] = 0ull;

    const float* inb = in + (size_t)n * CIN * IH * IW;
    for (int ci = 0; ci < CIN; ci++) {
        const float* inc = inb + (size_t)ci * IH * IW;
        const ulonglong2* wt = (const ulonglong2*)(sw + (size_t)ci * KK * CO_BLK);
#pragma unroll
        for (int ky = 0; ky < KS; ky++) {
            unsigned long long pv[COLS];
#pragma unroll
            for (int cx = 0; cx < COLS; cx++) {
                float val = (rok[ky] && cok[cx]) ? inc[roff[ky] + coff[cx]] : 0.f;
                pv[cx] = pk2(val, val);
            }
#pragma unroll
            for (int kx = 0; kx < KS; kx++) {
                const int t = ky * KS + kx;
#pragma unroll
                for (int q = 0; q < CO_BLK / 4; q++) {
                    ulonglong2 ww = wt[t * (CO_BLK / 4) + q];
#pragma unroll
                    for (int px = 0; px < PX; px++) {
                        fma2(acc[px][2 * q + 0], pv[px * STR + kx], ww.x);
                        fma2(acc[px][2 * q + 1], pv[px * STR + kx], ww.y);
                    }
                }
            }
        }
    }

    float* ob = out + ((size_t)n * COUT + co0) * OH * OW + p0;
#pragma unroll
    for (int j = 0; j < CO_BLK / 2; j++) {
        float b0 = bias[co0 + 2 * j], b1 = bias[co0 + 2 * j + 1];
        float r0[PX], r1[PX];
#pragma unroll
        for (int px = 0; px < PX; px++) {
            float2 f = upk2(acc[px][j]);
            r0[px] = f.x + b0; r1[px] = f.y + b1;
            if (RELU_OUT) { r0[px] = fmaxf(r0[px], 0.f); r1[px] = fmaxf(r1[px], 0.f); }
        }
        float* o0 = ob + (size_t)(2 * j + 0) * OH * OW;
        float* o1 = ob + (size_t)(2 * j + 1) * OH * OW;
        if (PX == 2) {
            *(float2*)o0 = make_float2(r0[0], r0[1 % PX]);
            *(float2*)o1 = make_float2(r1[0], r1[1 % PX]);
        } else {
#pragma unroll
            for (int px = 0; px < PX; px++) { o0[px] = r0[px]; o1[px] = r1[px]; }
        }
    }
}

// ---------------- transposed conv k=4 s=2 p=1 (gather) — tc2 only ----------------
template<int CIN, int COUT, int IH, int IW, int CO_BLK, int PX,
         bool RELU_IN, bool RELU_OUT>
__global__ void __launch_bounds__(256) convt_k(
    const float* __restrict__ in, const float* __restrict__ w,
    const float* __restrict__ bias, float* __restrict__ out)
{
    constexpr int OH = IH * 2, OW = IW * 2;
    extern __shared__ float sw[];

    const int n = blockIdx.z, co0 = blockIdx.y * CO_BLK, tid = threadIdx.x;
    for (int i = tid; i < CIN * 16 * CO_BLK; i += blockDim.x) {
        int co = i % CO_BLK, t = (i / CO_BLK) % 16, ci = i / (CO_BLK * 16);
        sw[i] = (co0 + co < COUT) ? w[((size_t)ci * COUT + (co0 + co)) * 16 + t] : 0.f;
    }
    __syncthreads();

    int p0 = (blockIdx.x * blockDim.x + tid) * PX;
    if (p0 >= OH * OW) return;
    int oy = p0 / OW, ox0 = p0 % OW;
    const int kpy = (oy + 1) & 1, kp0 = (ox0 + 1) & 1;

    int iy[2]; bool vy[2];
#pragma unroll
    for (int a = 0; a < 2; a++) {
        int ky = kpy + 2 * a, yy = oy + 1 - ky;
        iy[a] = yy >> 1; vy[a] = (yy >= 0) && (iy[a] < IH);
    }
    int ixp[PX][2]; bool vxp[PX][2];
#pragma unroll
    for (int px = 0; px < PX; px++) {
        int kpx = (kp0 + px) & 1;
#pragma unroll
        for (int b = 0; b < 2; b++) {
            int kx = kpx + 2 * b, xx = ox0 + px + 1 - kx;
            ixp[px][b] = xx >> 1; vxp[px][b] = (xx >= 0) && (ixp[px][b] < IW);
        }
    }

    unsigned long long acc[PX][CO_BLK / 2];
#pragma unroll
    for (int px = 0; px < PX; px++)
#pragma unroll
        for (int j = 0; j < CO_BLK / 2; j++) acc[px][j] = 0ull;

    const float* inb = in + (size_t)n * CIN * IH * IW;
    for (int ci = 0; ci < CIN; ci++) {
        const float* inc = inb + (size_t)ci * IH * IW;
        unsigned long long pv[PX][4];
#pragma unroll
        for (int px = 0; px < PX; px++)
#pragma unroll
            for (int a = 0; a < 2; a++)
#pragma unroll
                for (int b = 0; b < 2; b++) {
                    float val = 0.f;
                    if (vy[a] && vxp[px][b]) val = inc[iy[a] * IW + ixp[px][b]];
                    if (RELU_IN) val = fmaxf(val, 0.f);
                    pv[px][a * 2 + b] = pk2(val, val);
                }
        const ulonglong2* wt = (const ulonglong2*)(sw + (size_t)ci * 16 * CO_BLK);
#pragma unroll
        for (int g = 0; g < 2; g++) {
            const int kpxg = (kp0 + g) & 1;
#pragma unroll
            for (int a = 0; a < 2; a++)
#pragma unroll
                for (int b = 0; b < 2; b++) {
                    const int t = (kpy + 2 * a) * 4 + (kpxg + 2 * b);
#pragma unroll
                    for (int q = 0; q < CO_BLK / 4; q++) {
                        ulonglong2 ww = wt[t * (CO_BLK / 4) + q];
#pragma unroll
                        for (int px = g; px < PX; px += 2) {
                            fma2(acc[px][2 * q + 0], pv[px][a * 2 + b], ww.x);
                            fma2(acc[px][2 * q + 1], pv[px][a * 2 + b], ww.y);
                        }
                    }
                }
        }
    }

    float* ob = out + ((size_t)n * COUT + co0) * OH * OW + p0;
#pragma unroll
    for (int j = 0; j < CO_BLK / 2; j++) {
        float b0 = (co0 + 2 * j < COUT) ? bias[co0 + 2 * j] : 0.f;
        float b1 = (co0 + 2 * j + 1 < COUT) ? bias[co0 + 2 * j + 1] : 0.f;
        float r0[PX], r1[PX];
#pragma unroll
        for (int px = 0; px < PX; px++) {
            float2 f = upk2(acc[px][j]);
            r0[px] = f.x + b0; r1[px] = f.y + b1;
            if (RELU_OUT) { r0[px] = fmaxf(r0[px], 0.f); r1[px] = fmaxf(r1[px], 0.f); }
        }
        float* o0 = ob + (size_t)(2 * j + 0) * OH * OW;
        float* o1 = ob + (size_t)(2 * j + 1) * OH * OW;
#pragma unroll
        for (int px = 0; px < PX; px++) {
            if (co0 + 2 * j + 0 < COUT) o0[px] = r0[px];
            if (co0 + 2 * j + 1 < COUT) o1[px] = r1[px];
        }
    }
}

// ---------------- VQ ----------------
__global__ void vq_init_k(const float* __restrict__ E, float* __restrict__ enorm,
                          float* __restrict__ counts, float* __restrict__ sqsum)
{
    int k = blockIdx.x * blockDim.x + threadIdx.x;
    if (k < KCODES) {
        float s = 0.f;
#pragma unroll
        for (int d = 0; d < DDIM; d++) { float e = E[k * DDIM + d]; s += e * e; }
        enorm[k] = s; counts[k] = 0.f;
    }
    if (k == 0) sqsum[0] = 0.f;
}

__global__ void vq_k(const float* __restrict__ ze, const float* __restrict__ E,
                     const float* __restrict__ enorm, float* __restrict__ zq,
                     float* __restrict__ counts, float* __restrict__ sqsum)
{
    __shared__ float sE[128 * DDIM];
    __shared__ float sN[128];
    __shared__ float sred[8];

    const int tid = threadIdx.x;
    const int r = blockIdx.x * blockDim.x + tid;
    const int n = r >> 10, hw = r & 1023;

    const float* zb = ze + (size_t)n * DDIM * 1024 + hw;
    float z[DDIM];
#pragma unroll
    for (int d = 0; d < DDIM; d++) z[d] = zb[(size_t)d * 1024];
    float zn = 0.f;
#pragma unroll
    for (int d = 0; d < DDIM; d++) zn += z[d] * z[d];

    float best = 3.4e38f; int bidx = 0;
    for (int c = 0; c < KCODES / 128; c++) {
        __syncthreads();
        for (int i = tid; i < 128 * DDIM; i += blockDim.x) sE[i] = E[c * 128 * DDIM + i];
        for (int i = tid; i < 128; i += blockDim.x) sN[i] = enorm[c * 128 + i];
        __syncthreads();
        for (int k = 0; k < 128; k++) {
            const float4* e4 = (const float4*)(sE + k * DDIM);
            float a0 = 0.f, a1 = 0.f, a2 = 0.f, a3 = 0.f;
#pragma unroll
            for (int m = 0; m < DDIM / 4; m++) {
                float4 e = e4[m];
                a0 += z[4 * m + 0] * e.x; a1 += z[4 * m + 1] * e.y;
                a2 += z[4 * m + 2] * e.z; a3 += z[4 * m + 3] * e.w;
            }
            float dist = zn + sN[k] - 2.f * ((a0 + a1) + (a2 + a3));
            if (dist < best) { best = dist; bidx = c * 128 + k; }
        }
    }

    float local = 0.f;
    const float* eb = E + (size_t)bidx * DDIM;
    float* zqb = zq + (size_t)n * DDIM * 1024 + hw;
#pragma unroll
    for (int d = 0; d < DDIM; d++) {
        float e = eb[d];
        zqb[(size_t)d * 1024] = e;
        float df = e - z[d];
        local += df * df;
    }
    atomicAdd(&counts[bidx], 1.f);
#pragma unroll
    for (int o = 16; o; o >>= 1) local += __shfl_down_sync(0xffffffffu, local, o);
    if ((tid & 31) == 0) sred[tid >> 5] = local;
    __syncthreads();
    if (tid < 8) {
        local = sred[tid];
#pragma unroll
        for (int o = 4; o; o >>= 1) local += __shfl_down_sync(0xffu, local, o);
        if (tid == 0) atomicAdd(sqsum, local);
    }
}

__global__ void finalize_k(const float* __restrict__ counts, const float* __restrict__ sqsum,
                           float* __restrict__ out)
{
    __shared__ float sred[16];
    int tid = threadIdx.x;
    float p = counts[tid] * (1.f / 65536.f);
    float term = -p * log2f(p + 1e-10f);
#pragma unroll
    for (int o = 16; o; o >>= 1) term += __shfl_down_sync(0xffffffffu, term, o);
    if ((tid & 31) == 0) sred[tid >> 5] = term;
    __syncthreads();
    if (tid < 16) {
        term = sred[tid];
#pragma unroll
        for (int o = 8; o; o >>= 1) term += __shfl_down_sync(0xffffu, term, o);
        if (tid == 0) {
            float mse = sqsum[0] / (65536.f * 64.f);
            const int base = 1 + BATCH * 3 * 128 * 128;
            out[0] = 1.25f * mse;
            out[base + 0] = mse;
            out[base + 1] = mse;
            out[base + 2] = exp2f(term);
        }
    }
}

// ---------------- launch ----------------
extern "C" void kernel_launch(void* const* d_in, const int* in_sizes, int n_in,
                              void* d_out, int out_size)
{
    const float* x        = (const float*)d_in[0];
    const float* enc_w1   = (const float*)d_in[1];
    const float* enc_b1   = (const float*)d_in[2];
    const float* enc_w2   = (const float*)d_in[3];
    const float* enc_b2   = (const float*)d_in[4];
    const float* enc_w3   = (const float*)d_in[5];
    const float* enc_b3   = (const float*)d_in[6];
    const float* enc_w4   = (const float*)d_in[7];
    const float* enc_b4   = (const float*)d_in[8];
    const float* enc_rw1  = (const float*)d_in[9];
    const float* enc_rw2  = (const float*)d_in[10];
    const float* enc_adjw = (const float*)d_in[11];
    const float* enc_adjb = (const float*)d_in[12];
    const float* E        = (const float*)d_in[13];
    const float* dec_adjw = (const float*)d_in[14];
    const float* dec_adjb = (const float*)d_in[15];
    const float* dec_rw1  = (const float*)d_in[16];
    const float* dec_rw2  = (const float*)d_in[17];
    const float* tc1_w    = (const float*)d_in[18];
    const float* tc1_b    = (const float*)d_in[19];
    const float* tc2_w    = (const float*)d_in[20];
    const float* tc2_b    = (const float*)d_in[21];

    float* out   = (float*)d_out;
    float* recon = out + 1;

    float *h1, *a, *b, *mid, *ze, *zq, *enorm, *counts, *sqsum;
    __nv_bfloat16 *whi, *wlo;
    cudaGetSymbolAddress((void**)&h1, d_h1);
    cudaGetSymbolAddress((void**)&a, d_a);
    cudaGetSymbolAddress((void**)&b, d_b);
    cudaGetSymbolAddress((void**)&mid, d_mid);
    cudaGetSymbolAddress((void**)&ze, d_ze);
    cudaGetSymbolAddress((void**)&zq, d_zq);
    cudaGetSymbolAddress((void**)&enorm, d_enorm);
    cudaGetSymbolAddress((void**)&counts, d_counts);
    cudaGetSymbolAddress((void**)&sqsum, d_sqsum);
    cudaGetSymbolAddress((void**)&whi, d_whi);
    cudaGetSymbolAddress((void**)&wlo, d_wlo);

    const size_t O_W3 = 0, O_W4 = 147456, O_R1E0 = 294912, O_R1E1 = 368640;
    const size_t O_R2E0 = 442368, O_R2E1 = 450560, O_ADJ = 458752, O_DADJ = 466944;
    const size_t O_R1D0 = 540672, O_R1D1 = 614400, O_R2D0 = 688128, O_R2D1 = 696320;
    const size_t O_TC1 = 704512, O_C2 = 835584;

    {
        static const struct { int off, size, cout, cin, kk; } segs[12] = {
            {0, 147456, 128, 128, 9}, {147456, 147456, 128, 128, 9},
            {294912, 73728, 64, 128, 9}, {368640, 73728, 64, 128, 9},
            {442368, 8192, 128, 64, 1}, {450560, 8192, 128, 64, 1},
            {458752, 8192, 64, 128, 1}, {466944, 73728, 128, 64, 9},
            {540672, 73728, 64, 128, 9}, {614400, 73728, 64, 128, 9},
            {688128, 8192, 128, 64, 1}, {696320, 8192, 128, 64, 1}};
        cudaMemcpyToSymbolAsync(c_wseg, segs, sizeof(segs), 0, cudaMemcpyHostToDevice);
    }
    WPrepArgs wa;
    wa.s[0] = enc_w3; wa.s[1] = enc_w4;
    wa.s[2] = enc_rw1; wa.s[3] = enc_rw1 + 64 * 128 * 9;
    wa.s[4] = enc_rw2; wa.s[5] = enc_rw2 + 128 * 64;
    wa.s[6] = enc_adjw; wa.s[7] = dec_adjw;
    wa.s[8] = dec_rw1; wa.s[9] = dec_rw1 + 64 * 128 * 9;
    wa.s[10] = dec_rw2; wa.s[11] = dec_rw2 + 128 * 64;
    wa.tc1 = tc1_w; wa.c2 = enc_w2;
    wprep_all_k<<<(966656 + 255) / 256, 256>>>(wa, whi, wlo);

    const int TPB = 256;
    const dim3 TG(8, 1, BATCH);

    conv_k<3, 64, 4, 2, 1, 128, 128, 16, 2, true>
        <<<dim3(4096 / (TPB * 2), 4, BATCH), TPB, 3 * 16 * 16 * 4>>>(x, enc_w1, enc_b1, h1);

    auto t3_128_relu = mconv2_k<128, 128, 3, false, true, true, false>;
    auto t3_128      = mconv2_k<128, 128, 3, false, false, true, false>;
    auto t3_r1       = mconv2_k<128, 64, 3, true, false, false, false>;
    auto t1_r2       = mconv2_k<64, 128, 1, true, false, false, true>;
    auto t1_adj      = mconv2_k<128, 64, 1, true, false, true, false>;
    auto t3_dadj     = mconv2_k<64, 128, 3, false, false, true, false>;
    cudaFuncSetAttribute((const void*)t3_128_relu, cudaFuncAttributeMaxDynamicSharedMemorySize, MC_SMEM);
    cudaFuncSetAttribute((const void*)t3_128, cudaFuncAttributeMaxDynamicSharedMemorySize, MC_SMEM);
    cudaFuncSetAttribute((const void*)t3_r1, cudaFuncAttributeMaxDynamicSharedMemorySize, MC_SMEM);
    cudaFuncSetAttribute((const void*)t1_r2, cudaFuncAttributeMaxDynamicSharedMemorySize, MC_SMEM);
    cudaFuncSetAttribute((const void*)t1_adj, cudaFuncAttributeMaxDynamicSharedMemorySize, MC_SMEM);
    cudaFuncSetAttribute((const void*)t3_dadj, cudaFuncAttributeMaxDynamicSharedMemorySize, MC_SMEM);
    cudaFuncSetAttribute((const void*)tmct_k, cudaFuncAttributeMaxDynamicSharedMemorySize, MC_SMEM);
    cudaFuncSetAttribute((const void*)c2m_k, cudaFuncAttributeMaxDynamicSharedMemorySize, MC_SMEM);

    c2m_k<<<TG, TPB, MC_SMEM>>>(h1, whi + O_C2, wlo + O_C2, enc_b2, a);

    t3_128_relu<<<TG, TPB, MC_SMEM>>>(a, whi + O_W3, wlo + O_W3, enc_b3, nullptr, b);
    t3_128<<<TG, TPB, MC_SMEM>>>(b, whi + O_W4, wlo + O_W4, enc_b4, nullptr, a);
    t3_r1<<<TG, TPB, MC_SMEM>>>(a, whi + O_R1E0, wlo + O_R1E0, nullptr, nullptr, mid);
    t1_r2<<<TG, TPB, MC_SMEM>>>(mid, whi + O_R2E0, wlo + O_R2E0, nullptr, a, a);
    t3_r1<<<TG, TPB, MC_SMEM>>>(a, whi + O_R1E1, wlo + O_R1E1, nullptr, nullptr, mid);
    t1_r2<<<TG, TPB, MC_SMEM>>>(mid, whi + O_R2E1, wlo + O_R2E1, nullptr, a, a);
    t1_adj<<<TG, TPB, MC_SMEM>>>(a, whi + O_ADJ, wlo + O_ADJ, enc_adjb, nullptr, ze);

    vq_init_k<<<2, 256>>>(E, enorm, counts, sqsum);
    vq_k<<<65536 / 256, 256>>>(ze, E, enorm, zq, counts, sqsum);

    t3_dadj<<<TG, TPB, MC_SMEM>>>(zq, whi + O_DADJ, wlo + O_DADJ, dec_adjb, nullptr, a);
    t3_r1<<<TG, TPB, MC_SMEM>>>(a, whi + O_R1D0, wlo + O_R1D0, nullptr, nullptr, mid);
    t1_r2<<<TG, TPB, MC_SMEM>>>(mid, whi + O_R2D0, wlo + O_R2D0, nullptr, a, a);
    t3_r1<<<TG, TPB, MC_SMEM>>>(a, whi + O_R1D1, wlo + O_R1D1, nullptr, nullptr, mid);
    t1_r2<<<TG, TPB, MC_SMEM>>>(mid, whi + O_R2D1, wlo + O_R2D1, nullptr, a, a);

    tmct_k<<<dim3(8, 4, BATCH), TPB, MC_SMEM>>>(a, whi + O_TC1, wlo + O_TC1, tc1_b, h1);
    convt_k<64, 3, 64, 64, 4, 4, false, false>
        <<<dim3(16384 / (TPB * 4), 1, BATCH), TPB, 64 * 16 * 4 * 4>>>(h1, tc2_w, tc2_b, recon);

    finalize_k<<<1, 512>>>(counts, sqsum, out);
}

// round 12
// speedup vs baseline: 1.0225x; 1.0225x over previous
#include <cuda_runtime.h>
#include <cuda_bf16.h>
#include <math.h>
#include <stdint.h>

#define BATCH 64
#define KCODES 512
#define DDIM 64

__device__ float d_h1 [BATCH * 64 * 64 * 64];
__device__ float d_a  [BATCH * 128 * 32 * 32];
__device__ float d_b  [BATCH * 128 * 32 * 32];
__device__ float d_mid[BATCH * 64 * 32 * 32];
__device__ float d_ze [BATCH * 64 * 32 * 32];
__device__ float d_zq [BATCH * 64 * 32 * 32];
__device__ float d_enorm [KCODES];
__device__ float d_counts[KCODES];
__device__ float d_sqsum[1];
__device__ __nv_bfloat16 d_whi[1 << 20];
__device__ __nv_bfloat16 d_wlo[1 << 20];

__device__ __forceinline__ uint32_t smem_u32(const void* p) {
    uint32_t a;
    asm("{ .reg .u64 t; cvta.to.shared.u64 t, %1; cvt.u32.u64 %0, t; }" : "=r"(a) : "l"(p));
    return a;
}
__device__ __forceinline__ void mma_bf16(float* c, const uint32_t* a, const uint32_t* b) {
    asm volatile(
        "mma.sync.aligned.m16n8k16.row.col.f32.bf16.bf16.f32 "
        "{%0,%1,%2,%3}, {%4,%5,%6,%7}, {%8,%9}, {%0,%1,%2,%3};"
        : "+f"(c[0]), "+f"(c[1]), "+f"(c[2]), "+f"(c[3])
        : "r"(a[0]), "r"(a[1]), "r"(a[2]), "r"(a[3]), "r"(b[0]), "r"(b[1]));
}
__device__ __forceinline__ void ldm4(uint32_t* a, uint32_t addr) {
    asm volatile("ldmatrix.sync.aligned.m8n8.x4.shared.b16 {%0,%1,%2,%3}, [%4];"
                 : "=r"(a[0]), "=r"(a[1]), "=r"(a[2]), "=r"(a[3]) : "r"(addr));
}
__device__ __forceinline__ void split2(float f0, float f1, uint32_t& hp, uint32_t& lp) {
    asm("cvt.rn.bf16x2.f32 %0, %1, %2;" : "=r"(hp) : "f"(f1), "f"(f0));
    float h0 = __uint_as_float(hp << 16);
    float h1 = __uint_as_float(hp & 0xffff0000u);
    asm("cvt.rn.bf16x2.f32 %0, %1, %2;" : "=r"(lp) : "f"(f1 - h1), "f"(f0 - h0));
}

// window: [6 rows][36 cols][64 ci] bf16, 128B/(row,col), granule(16B) XOR-swizzled by col&7
static constexpr int WBYTES = 6 * 36 * 128;   // 27648
static constexpr int MC_SMEM = 2 * WBYTES;    // 55296

template<int CIN, bool RELU_IN>
__device__ __forceinline__ void stage_window(const float* __restrict__ in,
                                             int n, int kc, int by,
                                             int wid, int lane, char* smem)
{
    if (wid >= 6) return;
    const int y = wid, cp = lane;
    const int y_in = by * 4 + y - 1;
    const bool yok = (y_in >= 0) && (y_in < 32);
    const uint32_t wordoff = (uint32_t)((cp & 3) << 2);
    const uint32_t g0 = (uint32_t)(cp >> 2);

    auto st = [&](int xc, uint32_t hp, uint32_t lp) {
        uint32_t off = (uint32_t)((y * 36 + xc) << 7) + (((g0 ^ (uint32_t)(xc & 7)) << 4)) + wordoff;
        *(uint32_t*)(smem + off) = hp;
        *(uint32_t*)(smem + WBYTES + off) = lp;
    };
    st(0, 0u, 0u); st(33, 0u, 0u); st(34, 0u, 0u); st(35, 0u, 0u);
    if (yok) {
        const float* p0 = in + ((size_t)n * CIN + kc * 64 + 2 * cp) * 1024 + y_in * 32;
#pragma unroll
        for (int j = 0; j < 8; j++) {
            float4 a4 = *(const float4*)(p0 + 4 * j);
            float4 b4 = *(const float4*)(p0 + 1024 + 4 * j);
            if (RELU_IN) {
                a4.x = fmaxf(a4.x, 0.f); a4.y = fmaxf(a4.y, 0.f);
                a4.z = fmaxf(a4.z, 0.f); a4.w = fmaxf(a4.w, 0.f);
                b4.x = fmaxf(b4.x, 0.f); b4.y = fmaxf(b4.y, 0.f);
                b4.z = fmaxf(b4.z, 0.f); b4.w = fmaxf(b4.w, 0.f);
            }
            float fa[4] = {a4.x, a4.y, a4.z, a4.w};
            float fb[4] = {b4.x, b4.y, b4.z, b4.w};
#pragma unroll
            for (int e = 0; e < 4; e++) {
                uint32_t hp, lp;
                split2(fa[e], fb[e], hp, lp);
                st(1 + 4 * j + e, hp, lp);
            }
        }
    } else {
#pragma unroll
        for (int xc = 1; xc <= 32; xc++) st(xc, 0u, 0u);
    }
}

__device__ __forceinline__ void stage_window_s2(const float* __restrict__ in,
                                                int n, int by, int sy, int sx,
                                                int wid, int lane, char* smem)
{
    if (wid >= 6) return;
    const int y = wid, cp = lane;
    const int r_w = by * 4 + y - 1;
    const bool yok = (r_w >= 0) && (r_w < 32);
    const int iy = 2 * r_w + sy;
    const uint32_t wordoff = (uint32_t)((cp & 3) << 2);
    const uint32_t g0 = (uint32_t)(cp >> 2);

    auto st = [&](int xc, uint32_t hp, uint32_t lp) {
        uint32_t off = (uint32_t)((y * 36 + xc) << 7) + (((g0 ^ (uint32_t)(xc & 7)) << 4)) + wordoff;
        *(uint32_t*)(smem + off) = hp;
        *(uint32_t*)(smem + WBYTES + off) = lp;
    };
    st(0, 0u, 0u); st(33, 0u, 0u); st(34, 0u, 0u); st(35, 0u, 0u);
    if (yok) {
        const float* p0 = in + ((size_t)n * 64 + 2 * cp) * 4096 + iy * 64;
#pragma unroll
        for (int j = 0; j < 16; j++) {
            float4 a4 = *(const float4*)(p0 + 4 * j);
            float4 b4 = *(const float4*)(p0 + 4096 + 4 * j);
            float fa0 = sx ? a4.y : a4.x, fa1 = sx ? a4.w : a4.z;
            float fb0 = sx ? b4.y : b4.x, fb1 = sx ? b4.w : b4.z;
            uint32_t hp, lp;
            split2(fa0, fb0, hp, lp); st(1 + 2 * j, hp, lp);
            split2(fa1, fb1, hp, lp); st(2 + 2 * j, hp, lp);
        }
    } else {
#pragma unroll
        for (int xc = 1; xc <= 32; xc++) st(xc, 0u, 0u);
    }
}

// ---------------- merged weight prep ----------------
struct WPrepArgs {
    const float* s[12];
    const float* tc1;
    const float* c2;
};
__constant__ struct { int off, size, cout, cin, kk; } c_wseg[12];

__global__ void wprep_all_k(WPrepArgs a, __nv_bfloat16* __restrict__ hi, __nv_bfloat16* __restrict__ lo)
{
    const int O_TC1 = 704512, O_C2 = 835584, TOT = 966656;
    int i = blockIdx.x * 256 + threadIdx.x;
    if (i >= TOT) return;
    float f;
    if (i >= O_C2) {
        int j = i - O_C2;
        int ci = j & 63, co = (j >> 6) & 127, g = j >> 13;
        int sg = g >> 2, jt = g & 3;
        int sy = sg >> 1, sx = sg & 1, jy = jt >> 1, jx = jt & 1;
        int ky = 2 * jy + (1 - sy), kx = 2 * jx + (1 - sx);
        f = a.c2[((co * 64 + ci) * 4 + ky) * 4 + kx];
    } else if (i >= O_TC1) {
        int j = i - O_TC1;
        int ci = j & 127, co = (j >> 7) & 63, g = j >> 13;
        int pz = g >> 2, jt = g & 3;
        int py = pz >> 1, px = pz & 1, jy = jt >> 1, jx = jt & 1;
        int ky = (1 - py) + 2 * jy, kx = (1 - px) + 2 * jx;
        f = a.tc1[((ci * 64 + co) * 4 + ky) * 4 + kx];
    } else {
        int sidx = 0;
#pragma unroll
        for (int q = 1; q < 12; q++)
            if (i >= c_wseg[q].off) sidx = q;
        int j = i - c_wseg[sidx].off;
        int cin = c_wseg[sidx].cin, cout = c_wseg[sidx].cout, kk = c_wseg[sidx].kk;
        int ci = j % cin, co = (j / cin) % cout, t = j / (cin * cout);
        f = a.s[sidx][((size_t)co * cin + ci) * kk + t];
    }
    __nv_bfloat16 h = __float2bfloat16(f);
    hi[i] = h;
    lo[i] = __float2bfloat16(f - __bfloat162float(h));
}

// ---------------- direct-ldmatrix mma conv, warp tile = MT m-tiles x 32 co ----------------
// A-fragments loaded once per (t,k16) for all MT tiles; B streamed per f.
template<int CIN, int COUT, int KS, bool RELU_IN, bool RELU_OUT, bool HAS_BIAS, bool ADD_RES>
__global__ void __launch_bounds__(256, 2) mconv2_k(
    const float* __restrict__ in,
    const __nv_bfloat16* __restrict__ whi, const __nv_bfloat16* __restrict__ wlo,
    const float* __restrict__ bias, const float* __restrict__ res,
    float* __restrict__ out)
{
    constexpr int KCH = CIN / 64;
    constexpr int CW = COUT / 32;
    constexpr int MT = CW;
    constexpr int NF = 4;
    extern __shared__ char smem[];
    const uint32_t sH = smem_u32(smem), sL = sH + WBYTES;

    const int tid = threadIdx.x, wid = tid >> 5, lane = tid & 31;
    const int by = blockIdx.x, n = blockIdx.z;
    const int mg = wid / CW, cg = wid % CW;
    const int cobase = cg * 32;
    const int rowidx = ((lane >> 3) & 1) * 8 + (lane & 7);
    const int khalf = lane >> 4;

    float acc[MT][NF][4];
#pragma unroll
    for (int m = 0; m < MT; m++)
#pragma unroll
        for (int f = 0; f < NF; f++)
#pragma unroll
            for (int k = 0; k < 4; k++) acc[m][f][k] = 0.f;

    for (int kc = 0; kc < KCH; kc++) {
        if (kc) __syncthreads();
        stage_window<CIN, RELU_IN>(in, n, kc, by, wid, lane, smem);
        __syncthreads();

        for (int t = 0; t < KS * KS; t++) {
            const int dy = (KS == 1) ? 1 : t / KS;
            const int dx = (KS == 1) ? 1 : t % KS;
            const int cx = rowidx + dx;
            const uint32_t cx7 = (uint32_t)(cx & 7);
#pragma unroll
            for (int k16 = 0; k16 < 4; k16++) {
                const uint32_t gsw = (((uint32_t)(k16 * 2 + khalf) ^ cx7) << 4);
                uint32_t ah[MT][4], al[MT][4];
#pragma unroll
                for (int m = 0; m < MT; m++) {
                    const int mm = mg * MT + m;
                    uint32_t off = (uint32_t)((((mm >> 1) + dy) * 36 + (mm & 1) * 16 + cx) << 7) + gsw;
                    ldm4(ah[m], sH + off);
                    ldm4(al[m], sL + off);
                }
                const int kb = kc * 64 + k16 * 16 + (lane & 3) * 2;
#pragma unroll
                for (int f = 0; f < NF; f++) {
                    int co = cobase + f * 8 + (lane >> 2);
                    size_t base = ((size_t)t * COUT + co) * CIN + kb;
                    uint32_t bh[2], bl[2];
                    bh[0] = *(const uint32_t*)(whi + base);
                    bh[1] = *(const uint32_t*)(whi + base + 8);
                    bl[0] = *(const uint32_t*)(wlo + base);
                    bl[1] = *(const uint32_t*)(wlo + base + 8);
#pragma unroll
                    for (int m = 0; m < MT; m++) {
                        mma_bf16(acc[m][f], ah[m], bh);
                        mma_bf16(acc[m][f], ah[m], bl);
                        mma_bf16(acc[m][f], al[m], bh);
                    }
                }
            }
        }
    }

    const int r0 = lane >> 2, c0 = (lane & 3) * 2;
#pragma unroll
    for (int m = 0; m < MT; m++)
#pragma unroll
        for (int f = 0; f < NF; f++) {
            const int mm = mg * MT + m;
            int co = cobase + f * 8 + c0;
            int gp = by * 128 + mm * 16 + r0;
            float b0v = HAS_BIAS ? bias[co] : 0.f;
            float b1v = HAS_BIAS ? bias[co + 1] : 0.f;
            float v00 = acc[m][f][0] + b0v, v01 = acc[m][f][1] + b1v;
            float v10 = acc[m][f][2] + b0v, v11 = acc[m][f][3] + b1v;
            size_t o0 = ((size_t)n * COUT + co) * 1024 + gp;
            size_t o1 = ((size_t)n * COUT + co + 1) * 1024 + gp;
            if (ADD_RES) {
                v00 += res[o0]; v01 += res[o1];
                v10 += res[o0 + 8]; v11 += res[o1 + 8];
            }
            if (RELU_OUT) {
                v00 = fmaxf(v00, 0.f); v01 = fmaxf(v01, 0.f);
                v10 = fmaxf(v10, 0.f); v11 = fmaxf(v11, 0.f);
            }
            out[o0] = v00; out[o1] = v01;
            out[o0 + 8] = v10; out[o1 + 8] = v11;
        }
}

// ---------------- conv2 as tensor: 4 parity subgrids x 2x2 taps ----------------
__global__ void __launch_bounds__(256, 2) c2m_k(
    const float* __restrict__ in,
    const __nv_bfloat16* __restrict__ whi, const __nv_bfloat16* __restrict__ wlo,
    const float* __restrict__ bias, float* __restrict__ out)
{
    constexpr int COUT = 128, CW = 4, MT = 4, NF = 4;
    extern __shared__ char smem[];
    const uint32_t sH = smem_u32(smem), sL = sH + WBYTES;

    const int tid = threadIdx.x, wid = tid >> 5, lane = tid & 31;
    const int by = blockIdx.x, n = blockIdx.z;
    const int mg = wid / CW, cg = wid % CW;
    const int cobase = cg * 32;
    const int rowidx = ((lane >> 3) & 1) * 8 + (lane & 7);
    const int khalf = lane >> 4;

    float acc[MT][NF][4];
#pragma unroll
    for (int m = 0; m < MT; m++)
#pragma unroll
        for (int f = 0; f < NF; f++)
#pragma unroll
            for (int k = 0; k < 4; k++) acc[m][f][k] = 0.f;

    for (int sg = 0; sg < 4; sg++) {
        const int sy = sg >> 1, sx = sg & 1;
        if (sg) __syncthreads();
        stage_window_s2(in, n, by, sy, sx, wid, lane, smem);
        __syncthreads();

        for (int jt = 0; jt < 4; jt++) {
            const int jy = jt >> 1, jx = jt & 1;
            const int dy = jy + 1 - sy;
            const int dx = jx + 1 - sx;
            const int cx = rowidx + dx;
            const uint32_t cx7 = (uint32_t)(cx & 7);
            const int g = sg * 4 + jt;
#pragma unroll
            for (int k16 = 0; k16 < 4; k16++) {
                const uint32_t gsw = (((uint32_t)(k16 * 2 + khalf) ^ cx7) << 4);
                uint32_t ah[MT][4], al[MT][4];
#pragma unroll
                for (int m = 0; m < MT; m++) {
                    const int mm = mg * MT + m;
                    uint32_t off = (uint32_t)((((mm >> 1) + dy) * 36 + (mm & 1) * 16 + cx) << 7) + gsw;
                    ldm4(ah[m], sH + off);
                    ldm4(al[m], sL + off);
                }
                const int kb = k16 * 16 + (lane & 3) * 2;
#pragma unroll
                for (int f = 0; f < NF; f++) {
                    int co = cobase + f * 8 + (lane >> 2);
                    size_t base = ((size_t)g * COUT + co) * 64 + kb;
                    uint32_t bh[2], bl[2];
                    bh[0] = *(const uint32_t*)(whi + base);
                    bh[1] = *(const uint32_t*)(whi + base + 8);
                    bl[0] = *(const uint32_t*)(wlo + base);
                    bl[1] = *(const uint32_t*)(wlo + base + 8);
#pragma unroll
                    for (int m = 0; m < MT; m++) {
                        mma_bf16(acc[m][f], ah[m], bh);
                        mma_bf16(acc[m][f], ah[m], bl);
                        mma_bf16(acc[m][f], al[m], bh);
                    }
                }
            }
        }
    }

    const int r0 = lane >> 2, c0 = (lane & 3) * 2;
#pragma unroll
    for (int m = 0; m < MT; m++)
#pragma unroll
        for (int f = 0; f < NF; f++) {
            const int mm = mg * MT + m;
            int co = cobase + f * 8 + c0;
            int gp = by * 128 + mm * 16 + r0;
            float b0v = bias[co], b1v = bias[co + 1];
            float v00 = fmaxf(acc[m][f][0] + b0v, 0.f);
            float v01 = fmaxf(acc[m][f][1] + b1v, 0.f);
            float v10 = fmaxf(acc[m][f][2] + b0v, 0.f);
            float v11 = fmaxf(acc[m][f][3] + b1v, 0.f);
            size_t o0 = ((size_t)n * COUT + co) * 1024 + gp;
            size_t o1 = ((size_t)n * COUT + co + 1) * 1024 + gp;
            out[o0] = v00; out[o1] = v01;
            out[o0 + 8] = v10; out[o1 + 8] = v11;
        }
}

// ---------------- tc1 as tensor convT ----------------
__global__ void __launch_bounds__(256, 2) tmct_k(
    const float* __restrict__ in,
    const __nv_bfloat16* __restrict__ whi, const __nv_bfloat16* __restrict__ wlo,
    const float* __restrict__ bias, float* __restrict__ out)
{
    constexpr int CIN = 128, COUT = 64, CW = 2, MT = 2, NF = 4;
    extern __shared__ char smem[];
    const uint32_t sH = smem_u32(smem), sL = sH + WBYTES;

    const int tid = threadIdx.x, wid = tid >> 5, lane = tid & 31;
    const int by = blockIdx.x, pz = blockIdx.y, n = blockIdx.z;
    const int py = pz >> 1, px = pz & 1;
    const int mg = wid / CW, cg = wid % CW;
    const int cobase = cg * 32;
    const int rowidx = ((lane >> 3) & 1) * 8 + (lane & 7);
    const int khalf = lane >> 4;

    float acc[MT][NF][4];
#pragma unroll
    for (int m = 0; m < MT; m++)
#pragma unroll
        for (int f = 0; f < NF; f++)
#pragma unroll
            for (int k = 0; k < 4; k++) acc[m][f][k] = 0.f;

    for (int kc = 0; kc < 2; kc++) {
        if (kc) __syncthreads();
        stage_window<CIN, true>(in, n, kc, by, wid, lane, smem);
        __syncthreads();

        for (int jt = 0; jt < 4; jt++) {
            const int jy = jt >> 1, jx = jt & 1;
            const int dy = 1 - jy + py;
            const int dx = 1 - jx + px;
            const int cx = rowidx + dx;
            const uint32_t cx7 = (uint32_t)(cx & 7);
            const int g = pz * 4 + jt;
#pragma unroll
            for (int k16 = 0; k16 < 4; k16++) {
                const uint32_t gsw = (((uint32_t)(k16 * 2 + khalf) ^ cx7) << 4);
                uint32_t ah[MT][4], al[MT][4];
#pragma unroll
                for (int m = 0; m < MT; m++) {
                    const int mm = mg * MT + m;
                    uint32_t off = (uint32_t)((((mm >> 1) + dy) * 36 + (mm & 1) * 16 + cx) << 7) + gsw;
                    ldm4(ah[m], sH + off);
                    ldm4(al[m], sL + off);
                }
                const int kb = kc * 64 + k16 * 16 + (lane & 3) * 2;
#pragma unroll
                for (int f = 0; f < NF; f++) {
                    int co = cobase + f * 8 + (lane >> 2);
                    size_t base = ((size_t)g * COUT + co) * CIN + kb;
                    uint32_t bh[2], bl[2];
                    bh[0] = *(const uint32_t*)(whi + base);
                    bh[1] = *(const uint32_t*)(whi + base + 8);
                    bl[0] = *(const uint32_t*)(wlo + base);
                    bl[1] = *(const uint32_t*)(wlo + base + 8);
#pragma unroll
                    for (int m = 0; m < MT; m++) {
                        mma_bf16(acc[m][f], ah[m], bh);
                        mma_bf16(acc[m][f], ah[m], bl);
                        mma_bf16(acc[m][f], al[m], bh);
                    }
                }
            }
        }
    }

    const int r0 = lane >> 2, c0 = (lane & 3) * 2;
#pragma unroll
    for (int m = 0; m < MT; m++)
#pragma unroll
        for (int f = 0; f < NF; f++) {
            const int mm = mg * MT + m;
            int p = mm * 16 + r0;
            int co = cobase + f * 8 + c0;
            int ga = by * 4 + (p >> 5), gb = p & 31;
            int oy = 2 * ga + py, ox = 2 * gb + px;
            float b0v = bias[co], b1v = bias[co + 1];
            float v00 = fmaxf(acc[m][f][0] + b0v, 0.f);
            float v01 = fmaxf(acc[m][f][1] + b1v, 0.f);
            float v10 = fmaxf(acc[m][f][2] + b0v, 0.f);
            float v11 = fmaxf(acc[m][f][3] + b1v, 0.f);
            size_t o00 = (((size_t)n * 64 + co) * 64 + oy) * 64 + ox;
            out[o00] = v00; out[o00 + 4096] = v01;
            out[o00 + 16] = v10; out[o00 + 4096 + 16] = v11;
        }
}

// ---------------- f32x2 helpers ----------------
__device__ __forceinline__ unsigned long long pk2(float a, float b) {
    unsigned long long r;
    asm("mov.b64 %0, {%1, %2};" : "=l"(r) : "f"(a), "f"(b));
    return r;
}
__device__ __forceinline__ void fma2(unsigned long long& d, unsigned long long a, unsigned long long b) {
    asm("fma.rn.f32x2 %0, %1, %2, %0;" : "+l"(d) : "l"(a), "l"(b));
}
__device__ __forceinline__ float2 upk2(unsigned long long a) {
    float2 f;
    asm("mov.b64 {%0, %1}, %2;" : "=f"(f.x), "=f"(f.y) : "l"(a));
    return f;
}

// ---------------- generic direct conv (conv1 only) ----------------
template<int CIN, int COUT, int KS, int STR, int PAD, int IH, int IW, int CO_BLK, int PX,
         bool RELU_OUT>
__global__ void __launch_bounds__(256) conv_k(
    const float* __restrict__ in, const float* __restrict__ w,
    const float* __restrict__ bias, float* __restrict__ out)
{
    constexpr int OH = (IH + 2 * PAD - KS) / STR + 1;
    constexpr int OW = (IW + 2 * PAD - KS) / STR + 1;
    constexpr int KK = KS * KS;
    constexpr int COLS = STR * (PX - 1) + KS;
    extern __shared__ float sw[];

    const int n = blockIdx.z, co0 = blockIdx.y * CO_BLK, tid = threadIdx.x;
    for (int i = tid; i < CIN * KK * CO_BLK; i += blockDim.x) {
        int co = i % CO_BLK, t = (i / CO_BLK) % KK, ci = i / (CO_BLK * KK);
        sw[i] = w[((size_t)(co0 + co) * CIN + ci) * KK + t];
    }
    __syncthreads();

    int p0 = (blockIdx.x * blockDim.x + tid) * PX;
    if (p0 >= OH * OW) return;
    int oy = p0 / OW, ox0 = p0 % OW;
    int iy0 = oy * STR - PAD, ix0 = ox0 * STR - PAD;

    bool rok[KS]; int roff[KS];
#pragma unroll
    for (int ky = 0; ky < KS; ky++) {
        int y = iy0 + ky; rok[ky] = (y >= 0) && (y < IH); roff[ky] = y * IW;
    }
    bool cok[COLS]; int coff[COLS];
#pragma unroll
    for (int cx = 0; cx < COLS; cx++) {
        int x = ix0 + cx; cok[cx] = (x >= 0) && (x < IW); coff[cx] = x;
    }

    unsigned long long acc[PX][CO_BLK / 2];
#pragma unroll
    for (int px = 0; px < PX; px++)
#pragma unroll
        for (int j = 0; j < CO_BLK / 2; j++) acc[px][j] = 0ull;

    const float* inb = in + (size_t)n * CIN * IH * IW;
    for (int ci = 0; ci < CIN; ci++) {
        const float* inc = inb + (size_t)ci * IH * IW;
        const ulonglong2* wt = (const ulonglong2*)(sw + (size_t)ci * KK * CO_BLK);
#pragma unroll
        for (int ky = 0; ky < KS; ky++) {
            unsigned long long pv[COLS];
#pragma unroll
            for (int cx = 0; cx < COLS; cx++) {
                float val = (rok[ky] && cok[cx]) ? inc[roff[ky] + coff[cx]] : 0.f;
                pv[cx] = pk2(val, val);
            }
#pragma unroll
            for (int kx = 0; kx < KS; kx++) {
                const int t = ky * KS + kx;
#pragma unroll
                for (int q = 0; q < CO_BLK / 4; q++) {
                    ulonglong2 ww = wt[t * (CO_BLK / 4) + q];
#pragma unroll
                    for (int px = 0; px < PX; px++) {
                        fma2(acc[px][2 * q + 0], pv[px * STR + kx], ww.x);
                        fma2(acc[px][2 * q + 1], pv[px * STR + kx], ww.y);
                    }
                }
            }
        }
    }

    float* ob = out + ((size_t)n * COUT + co0) * OH * OW + p0;
#pragma unroll
    for (int j = 0; j < CO_BLK / 2; j++) {
        float b0 = bias[co0 + 2 * j], b1 = bias[co0 + 2 * j + 1];
        float r0[PX], r1[PX];
#pragma unroll
        for (int px = 0; px < PX; px++) {
            float2 f = upk2(acc[px][j]);
            r0[px] = f.x + b0; r1[px] = f.y + b1;
            if (RELU_OUT) { r0[px] = fmaxf(r0[px], 0.f); r1[px] = fmaxf(r1[px], 0.f); }
        }
        float* o0 = ob + (size_t)(2 * j + 0) * OH * OW;
        float* o1 = ob + (size_t)(2 * j + 1) * OH * OW;
        if (PX == 2) {
            *(float2*)o0 = make_float2(r0[0], r0[1 % PX]);
            *(float2*)o1 = make_float2(r1[0], r1[1 % PX]);
        } else {
#pragma unroll
            for (int px = 0; px < PX; px++) { o0[px] = r0[px]; o1[px] = r1[px]; }
        }
    }
}

// ---------------- transposed conv k=4 s=2 p=1 (gather) — tc2 only ----------------
template<int CIN, int COUT, int IH, int IW, int CO_BLK, int PX,
         bool RELU_IN, bool RELU_OUT>
__global__ void __launch_bounds__(256) convt_k(
    const float* __restrict__ in, const float* __restrict__ w,
    const float* __restrict__ bias, float* __restrict__ out)
{
    constexpr int OH = IH * 2, OW = IW * 2;
    extern __shared__ float sw[];

    const int n = blockIdx.z, co0 = blockIdx.y * CO_BLK, tid = threadIdx.x;
    for (int i = tid; i < CIN * 16 * CO_BLK; i += blockDim.x) {
        int co = i % CO_BLK, t = (i / CO_BLK) % 16, ci = i / (CO_BLK * 16);
        sw[i] = (co0 + co < COUT) ? w[((size_t)ci * COUT + (co0 + co)) * 16 + t] : 0.f;
    }
    __syncthreads();

    int p0 = (blockIdx.x * blockDim.x + tid) * PX;
    if (p0 >= OH * OW) return;
    int oy = p0 / OW, ox0 = p0 % OW;
    const int kpy = (oy + 1) & 1, kp0 = (ox0 + 1) & 1;

    int iy[2]; bool vy[2];
#pragma unroll
    for (int a = 0; a < 2; a++) {
        int ky = kpy + 2 * a, yy = oy + 1 - ky;
        iy[a] = yy >> 1; vy[a] = (yy >= 0) && (iy[a] < IH);
    }
    int ixp[PX][2]; bool vxp[PX][2];
#pragma unroll
    for (int px = 0; px < PX; px++) {
        int kpx = (kp0 + px) & 1;
#pragma unroll
        for (int b = 0; b < 2; b++) {
            int kx = kpx + 2 * b, xx = ox0 + px + 1 - kx;
            ixp[px][b] = xx >> 1; vxp[px][b] = (xx >= 0) && (ixp[px][b] < IW);
        }
    }

    unsigned long long acc[PX][CO_BLK / 2];
#pragma unroll
    for (int px = 0; px < PX; px++)
#pragma unroll
        for (int j = 0; j < CO_BLK / 2; j++) acc[px][j] = 0ull;

    const float* inb = in + (size_t)n * CIN * IH * IW;
    for (int ci = 0; ci < CIN; ci++) {
        const float* inc = inb + (size_t)ci * IH * IW;
        unsigned long long pv[PX][4];
#pragma unroll
        for (int px = 0; px < PX; px++)
#pragma unroll
            for (int a = 0; a < 2; a++)
#pragma unroll
                for (int b = 0; b < 2; b++) {
                    float val = 0.f;
                    if (vy[a] && vxp[px][b]) val = inc[iy[a] * IW + ixp[px][b]];
                    if (RELU_IN) val = fmaxf(val, 0.f);
                    pv[px][a * 2 + b] = pk2(val, val);
                }
        const ulonglong2* wt = (const ulonglong2*)(sw + (size_t)ci * 16 * CO_BLK);
#pragma unroll
        for (int g = 0; g < 2; g++) {
            const int kpxg = (kp0 + g) & 1;
#pragma unroll
            for (int a = 0; a < 2; a++)
#pragma unroll
                for (int b = 0; b < 2; b++) {
                    const int t = (kpy + 2 * a) * 4 + (kpxg + 2 * b);
#pragma unroll
                    for (int q = 0; q < CO_BLK / 4; q++) {
                        ulonglong2 ww = wt[t * (CO_BLK / 4) + q];
#pragma unroll
                        for (int px = g; px < PX; px += 2) {
                            fma2(acc[px][2 * q + 0], pv[px][a * 2 + b], ww.x);
                            fma2(acc[px][2 * q + 1], pv[px][a * 2 + b], ww.y);
                        }
                    }
                }
        }
    }

    float* ob = out + ((size_t)n * COUT + co0) * OH * OW + p0;
#pragma unroll
    for (int j = 0; j < CO_BLK / 2; j++) {
        float b0 = (co0 + 2 * j < COUT) ? bias[co0 + 2 * j] : 0.f;
        float b1 = (co0 + 2 * j + 1 < COUT) ? bias[co0 + 2 * j + 1] : 0.f;
        float r0[PX], r1[PX];
#pragma unroll
        for (int px = 0; px < PX; px++) {
            float2 f = upk2(acc[px][j]);
            r0[px] = f.x + b0; r1[px] = f.y + b1;
            if (RELU_OUT) { r0[px] = fmaxf(r0[px], 0.f); r1[px] = fmaxf(r1[px], 0.f); }
        }
        float* o0 = ob + (size_t)(2 * j + 0) * OH * OW;
        float* o1 = ob + (size_t)(2 * j + 1) * OH * OW;
#pragma unroll
        for (int px = 0; px < PX; px++) {
            if (co0 + 2 * j + 0 < COUT) o0[px] = r0[px];
            if (co0 + 2 * j + 1 < COUT) o1[px] = r1[px];
        }
    }
}

// ---------------- VQ ----------------
__global__ void vq_init_k(const float* __restrict__ E, float* __restrict__ enorm,
                          float* __restrict__ counts, float* __restrict__ sqsum)
{
    int k = blockIdx.x * blockDim.x + threadIdx.x;
    if (k < KCODES) {
        float s = 0.f;
#pragma unroll
        for (int d = 0; d < DDIM; d++) { float e = E[k * DDIM + d]; s += e * e; }
        enorm[k] = s; counts[k] = 0.f;
    }
    if (k == 0) sqsum[0] = 0.f;
}

__global__ void vq_k(const float* __restrict__ ze, const float* __restrict__ E,
                     const float* __restrict__ enorm, float* __restrict__ zq,
                     float* __restrict__ counts, float* __restrict__ sqsum)
{
    __shared__ float sE[128 * DDIM];
    __shared__ float sN[128];
    __shared__ float sred[8];

    const int tid = threadIdx.x;
    const int r = blockIdx.x * blockDim.x + tid;
    const int n = r >> 10, hw = r & 1023;

    const float* zb = ze + (size_t)n * DDIM * 1024 + hw;
    float z[DDIM];
#pragma unroll
    for (int d = 0; d < DDIM; d++) z[d] = zb[(size_t)d * 1024];
    float zn = 0.f;
#pragma unroll
    for (int d = 0; d < DDIM; d++) zn += z[d] * z[d];

    float best = 3.4e38f; int bidx = 0;
    for (int c = 0; c < KCODES / 128; c++) {
        __syncthreads();
        for (int i = tid; i < 128 * DDIM; i += blockDim.x) sE[i] = E[c * 128 * DDIM + i];
        for (int i = tid; i < 128; i += blockDim.x) sN[i] = enorm[c * 128 + i];
        __syncthreads();
        for (int k = 0; k < 128; k++) {
            const float4* e4 = (const float4*)(sE + k * DDIM);
            float a0 = 0.f, a1 = 0.f, a2 = 0.f, a3 = 0.f;
#pragma unroll
            for (int m = 0; m < DDIM / 4; m++) {
                float4 e = e4[m];
                a0 += z[4 * m + 0] * e.x; a1 += z[4 * m + 1] * e.y;
                a2 += z[4 * m + 2] * e.z; a3 += z[4 * m + 3] * e.w;
            }
            float dist = zn + sN[k] - 2.f * ((a0 + a1) + (a2 + a3));
            if (dist < best) { best = dist; bidx = c * 128 + k; }
        }
    }

    float local = 0.f;
    const float* eb = E + (size_t)bidx * DDIM;
    float* zqb = zq + (size_t)n * DDIM * 1024 + hw;
#pragma unroll
    for (int d = 0; d < DDIM; d++) {
        float e = eb[d];
        zqb[(size_t)d * 1024] = e;
        float df = e - z[d];
        local += df * df;
    }
    atomicAdd(&counts[bidx], 1.f);
#pragma unroll
    for (int o = 16; o; o >>= 1) local += __shfl_down_sync(0xffffffffu, local, o);
    if ((tid & 31) == 0) sred[tid >> 5] = local;
    __syncthreads();
    if (tid < 8) {
        local = sred[tid];
#pragma unroll
        for (int o = 4; o; o >>= 1) local += __shfl_down_sync(0xffu, local, o);
        if (tid == 0) atomicAdd(sqsum, local);
    }
}

__global__ void finalize_k(const float* __restrict__ counts, const float* __restrict__ sqsum,
                           float* __restrict__ out)
{
    __shared__ float sred[16];
    int tid = threadIdx.x;
    float p = counts[tid] * (1.f / 65536.f);
    float term = -p * log2f(p + 1e-10f);
#pragma unroll
    for (int o = 16; o; o >>= 1) term += __shfl_down_sync(0xffffffffu, term, o);
    if ((tid & 31) == 0) sred[tid >> 5] = term;
    __syncthreads();
    if (tid < 16) {
        term = sred[tid];
#pragma unroll
        for (int o = 8; o; o >>= 1) term += __shfl_down_sync(0xffffu, term, o);
        if (tid == 0) {
            float mse = sqsum[0] / (65536.f * 64.f);
            const int base = 1 + BATCH * 3 * 128 * 128;
            out[0] = 1.25f * mse;
            out[base + 0] = mse;
            out[base + 1] = mse;
            out[base + 2] = exp2f(term);
        }
    }
}

// ---------------- launch ----------------
extern "C" void kernel_launch(void* const* d_in, const int* in_sizes, int n_in,
                              void* d_out, int out_size)
{
    const float* x        = (const float*)d_in[0];
    const float* enc_w1   = (const float*)d_in[1];
    const float* enc_b1   = (const float*)d_in[2];
    const float* enc_w2   = (const float*)d_in[3];
    const float* enc_b2   = (const float*)d_in[4];
    const float* enc_w3   = (const float*)d_in[5];
    const float* enc_b3   = (const float*)d_in[6];
    const float* enc_w4   = (const float*)d_in[7];
    const float* enc_b4   = (const float*)d_in[8];
    const float* enc_rw1  = (const float*)d_in[9];
    const float* enc_rw2  = (const float*)d_in[10];
    const float* enc_adjw = (const float*)d_in[11];
    const float* enc_adjb = (const float*)d_in[12];
    const float* E        = (const float*)d_in[13];
    const float* dec_adjw = (const float*)d_in[14];
    const float* dec_adjb = (const float*)d_in[15];
    const float* dec_rw1  = (const float*)d_in[16];
    const float* dec_rw2  = (const float*)d_in[17];
    const float* tc1_w    = (const float*)d_in[18];
    const float* tc1_b    = (const float*)d_in[19];
    const float* tc2_w    = (const float*)d_in[20];
    const float* tc2_b    = (const float*)d_in[21];

    float* out   = (float*)d_out;
    float* recon = out + 1;

    float *h1, *a, *b, *mid, *ze, *zq, *enorm, *counts, *sqsum;
    __nv_bfloat16 *whi, *wlo;
    cudaGetSymbolAddress((void**)&h1, d_h1);
    cudaGetSymbolAddress((void**)&a, d_a);
    cudaGetSymbolAddress((void**)&b, d_b);
    cudaGetSymbolAddress((void**)&mid, d_mid);
    cudaGetSymbolAddress((void**)&ze, d_ze);
    cudaGetSymbolAddress((void**)&zq, d_zq);
    cudaGetSymbolAddress((void**)&enorm, d_enorm);
    cudaGetSymbolAddress((void**)&counts, d_counts);
    cudaGetSymbolAddress((void**)&sqsum, d_sqsum);
    cudaGetSymbolAddress((void**)&whi, d_whi);
    cudaGetSymbolAddress((void**)&wlo, d_wlo);

    const size_t O_W3 = 0, O_W4 = 147456, O_R1E0 = 294912, O_R1E1 = 368640;
    const size_t O_R2E0 = 442368, O_R2E1 = 450560, O_ADJ = 458752, O_DADJ = 466944;
    const size_t O_R1D0 = 540672, O_R1D1 = 614400, O_R2D0 = 688128, O_R2D1 = 696320;
    const size_t O_TC1 = 704512, O_C2 = 835584;

    {
        static const struct { int off, size, cout, cin, kk; } segs[12] = {
            {0, 147456, 128, 128, 9}, {147456, 147456, 128, 128, 9},
            {294912, 73728, 64, 128, 9}, {368640, 73728, 64, 128, 9},
            {442368, 8192, 128, 64, 1}, {450560, 8192, 128, 64, 1},
            {458752, 8192, 64, 128, 1}, {466944, 73728, 128, 64, 9},
            {540672, 73728, 64, 128, 9}, {614400, 73728, 64, 128, 9},
            {688128, 8192, 128, 64, 1}, {696320, 8192, 128, 64, 1}};
        cudaMemcpyToSymbolAsync(c_wseg, segs, sizeof(segs), 0, cudaMemcpyHostToDevice);
    }
    WPrepArgs wa;
    wa.s[0] = enc_w3; wa.s[1] = enc_w4;
    wa.s[2] = enc_rw1; wa.s[3] = enc_rw1 + 64 * 128 * 9;
    wa.s[4] = enc_rw2; wa.s[5] = enc_rw2 + 128 * 64;
    wa.s[6] = enc_adjw; wa.s[7] = dec_adjw;
    wa.s[8] = dec_rw1; wa.s[9] = dec_rw1 + 64 * 128 * 9;
    wa.s[10] = dec_rw2; wa.s[11] = dec_rw2 + 128 * 64;
    wa.tc1 = tc1_w; wa.c2 = enc_w2;
    wprep_all_k<<<(966656 + 255) / 256, 256>>>(wa, whi, wlo);

    const int TPB = 256;
    const dim3 TG(8, 1, BATCH);

    conv_k<3, 64, 4, 2, 1, 128, 128, 16, 2, true>
        <<<dim3(4096 / (TPB * 2), 4, BATCH), TPB, 3 * 16 * 16 * 4>>>(x, enc_w1, enc_b1, h1);

    auto t3_128_relu = mconv2_k<128, 128, 3, false, true, true, false>;
    auto t3_128      = mconv2_k<128, 128, 3, false, false, true, false>;
    auto t3_r1       = mconv2_k<128, 64, 3, true, false, false, false>;
    auto t1_r2       = mconv2_k<64, 128, 1, true, false, false, true>;
    auto t1_adj      = mconv2_k<128, 64, 1, true, false, true, false>;
    auto t3_dadj     = mconv2_k<64, 128, 3, false, false, true, false>;
    cudaFuncSetAttribute((const void*)t3_128_relu, cudaFuncAttributeMaxDynamicSharedMemorySize, MC_SMEM);
    cudaFuncSetAttribute((const void*)t3_128, cudaFuncAttributeMaxDynamicSharedMemorySize, MC_SMEM);
    cudaFuncSetAttribute((const void*)t3_r1, cudaFuncAttributeMaxDynamicSharedMemorySize, MC_SMEM);
    cudaFuncSetAttribute((const void*)t1_r2, cudaFuncAttributeMaxDynamicSharedMemorySize, MC_SMEM);
    cudaFuncSetAttribute((const void*)t1_adj, cudaFuncAttributeMaxDynamicSharedMemorySize, MC_SMEM);
    cudaFuncSetAttribute((const void*)t3_dadj, cudaFuncAttributeMaxDynamicSharedMemorySize, MC_SMEM);
    cudaFuncSetAttribute((const void*)tmct_k, cudaFuncAttributeMaxDynamicSharedMemorySize, MC_SMEM);
    cudaFuncSetAttribute((const void*)c2m_k, cudaFuncAttributeMaxDynamicSharedMemorySize, MC_SMEM);

    c2m_k<<<TG, TPB, MC_SMEM>>>(h1, whi + O_C2, wlo + O_C2, enc_b2, a);

    t3_128_relu<<<TG, TPB, MC_SMEM>>>(a, whi + O_W3, wlo + O_W3, enc_b3, nullptr, b);
    t3_128<<<TG, TPB, MC_SMEM>>>(b, whi + O_W4, wlo + O_W4, enc_b4, nullptr, a);
    t3_r1<<<TG, TPB, MC_SMEM>>>(a, whi + O_R1E0, wlo + O_R1E0, nullptr, nullptr, mid);
    t1_r2<<<TG, TPB, MC_SMEM>>>(mid, whi + O_R2E0, wlo + O_R2E0, nullptr, a, a);
    t3_r1<<<TG, TPB, MC_SMEM>>>(a, whi + O_R1E1, wlo + O_R1E1, nullptr, nullptr, mid);
    t1_r2<<<TG, TPB, MC_SMEM>>>(mid, whi + O_R2E1, wlo + O_R2E1, nullptr, a, a);
    t1_adj<<<TG, TPB, MC_SMEM>>>(a, whi + O_ADJ, wlo + O_ADJ, enc_adjb, nullptr, ze);

    vq_init_k<<<2, 256>>>(E, enorm, counts, sqsum);
    vq_k<<<65536 / 256, 256>>>(ze, E, enorm, zq, counts, sqsum);

    t3_dadj<<<TG, TPB, MC_SMEM>>>(zq, whi + O_DADJ, wlo + O_DADJ, dec_adjb, nullptr, a);
    t3_r1<<<TG, TPB, MC_SMEM>>>(a, whi + O_R1D0, wlo + O_R1D0, nullptr, nullptr, mid);
    t1_r2<<<TG, TPB, MC_SMEM>>>(mid, whi + O_R2D0, wlo + O_R2D0, nullptr, a, a);
    t3_r1<<<TG, TPB, MC_SMEM>>>(a, whi + O_R1D1, wlo + O_R1D1, nullptr, nullptr, mid);
    t1_r2<<<TG, TPB, MC_SMEM>>>(mid, whi + O_R2D1, wlo + O_R2D1, nullptr, a, a);

    tmct_k<<<dim3(8, 4, BATCH), TPB, MC_SMEM>>>(a, whi + O_TC1, wlo + O_TC1, tc1_b, h1);
    convt_k<64, 3, 64, 64, 4, 4, false, false>
        <<<dim3(16384 / (TPB * 4), 1, BATCH), TPB, 64 * 16 * 4 * 4>>>(h1, tc2_w, tc2_b, recon);

    finalize_k<<<1, 512>>>(counts, sqsum, out);
}

// round 13
// speedup vs baseline: 1.3935x; 1.3628x over previous
#include <cuda_runtime.h>
#include <cuda_bf16.h>
#include <math.h>
#include <stdint.h>

#define BATCH 64
#define KCODES 512
#define DDIM 64

__device__ float d_h1 [BATCH * 64 * 64 * 64];
__device__ float d_a  [BATCH * 128 * 32 * 32];
__device__ float d_b  [BATCH * 128 * 32 * 32];
__device__ float d_mid[BATCH * 64 * 32 * 32];
__device__ float d_ze [BATCH * 64 * 32 * 32];
__device__ float d_zq [BATCH * 64 * 32 * 32];
__device__ float d_enorm [KCODES];
__device__ float d_counts[KCODES];
__device__ float d_sqsum[1];
__device__ __nv_bfloat16 d_whi[1 << 20];
__device__ __nv_bfloat16 d_wlo[1 << 20];

__device__ __forceinline__ uint32_t smem_u32(const void* p) {
    uint32_t a;
    asm("{ .reg .u64 t; cvta.to.shared.u64 t, %1; cvt.u32.u64 %0, t; }" : "=r"(a) : "l"(p));
    return a;
}
__device__ __forceinline__ void mma_bf16(float* c, const uint32_t* a, const uint32_t* b) {
    asm volatile(
        "mma.sync.aligned.m16n8k16.row.col.f32.bf16.bf16.f32 "
        "{%0,%1,%2,%3}, {%4,%5,%6,%7}, {%8,%9}, {%0,%1,%2,%3};"
        : "+f"(c[0]), "+f"(c[1]), "+f"(c[2]), "+f"(c[3])
        : "r"(a[0]), "r"(a[1]), "r"(a[2]), "r"(a[3]), "r"(b[0]), "r"(b[1]));
}
__device__ __forceinline__ void ldm4(uint32_t* a, uint32_t addr) {
    asm volatile("ldmatrix.sync.aligned.m8n8.x4.shared.b16 {%0,%1,%2,%3}, [%4];"
                 : "=r"(a[0]), "=r"(a[1]), "=r"(a[2]), "=r"(a[3]) : "r"(addr));
}
__device__ __forceinline__ void split2(float f0, float f1, uint32_t& hp, uint32_t& lp) {
    asm("cvt.rn.bf16x2.f32 %0, %1, %2;" : "=r"(hp) : "f"(f1), "f"(f0));
    float h0 = __uint_as_float(hp << 16);
    float h1 = __uint_as_float(hp & 0xffff0000u);
    asm("cvt.rn.bf16x2.f32 %0, %1, %2;" : "=r"(lp) : "f"(f1 - h1), "f"(f0 - h0));
}

// window: [6 rows][36 cols][64 ci] bf16, 128B/(row,col), granule(16B) XOR-swizzled by col&7
static constexpr int WBYTES = 6 * 36 * 128;   // 27648
static constexpr int MC_SMEM = 2 * WBYTES;    // 55296

template<int CIN, bool RELU_IN>
__device__ __forceinline__ void stage_window(const float* __restrict__ in,
                                             int n, int kc, int by,
                                             int wid, int lane, char* smem)
{
    if (wid >= 6) return;
    const int y = wid, cp = lane;
    const int y_in = by * 4 + y - 1;
    const bool yok = (y_in >= 0) && (y_in < 32);
    const uint32_t wordoff = (uint32_t)((cp & 3) << 2);
    const uint32_t g0 = (uint32_t)(cp >> 2);

    auto st = [&](int xc, uint32_t hp, uint32_t lp) {
        uint32_t off = (uint32_t)((y * 36 + xc) << 7) + (((g0 ^ (uint32_t)(xc & 7)) << 4)) + wordoff;
        *(uint32_t*)(smem + off) = hp;
        *(uint32_t*)(smem + WBYTES + off) = lp;
    };
    st(0, 0u, 0u); st(33, 0u, 0u); st(34, 0u, 0u); st(35, 0u, 0u);
    if (yok) {
        const float* p0 = in + ((size_t)n * CIN + kc * 64 + 2 * cp) * 1024 + y_in * 32;
#pragma unroll
        for (int j = 0; j < 8; j++) {
            float4 a4 = *(const float4*)(p0 + 4 * j);
            float4 b4 = *(const float4*)(p0 + 1024 + 4 * j);
            if (RELU_IN) {
                a4.x = fmaxf(a4.x, 0.f); a4.y = fmaxf(a4.y, 0.f);
                a4.z = fmaxf(a4.z, 0.f); a4.w = fmaxf(a4.w, 0.f);
                b4.x = fmaxf(b4.x, 0.f); b4.y = fmaxf(b4.y, 0.f);
                b4.z = fmaxf(b4.z, 0.f); b4.w = fmaxf(b4.w, 0.f);
            }
            float fa[4] = {a4.x, a4.y, a4.z, a4.w};
            float fb[4] = {b4.x, b4.y, b4.z, b4.w};
#pragma unroll
            for (int e = 0; e < 4; e++) {
                uint32_t hp, lp;
                split2(fa[e], fb[e], hp, lp);
                st(1 + 4 * j + e, hp, lp);
            }
        }
    } else {
#pragma unroll
        for (int xc = 1; xc <= 32; xc++) st(xc, 0u, 0u);
    }
}

__device__ __forceinline__ void stage_window_s2(const float* __restrict__ in,
                                                int n, int by, int sy, int sx,
                                                int wid, int lane, char* smem)
{
    if (wid >= 6) return;
    const int y = wid, cp = lane;
    const int r_w = by * 4 + y - 1;
    const bool yok = (r_w >= 0) && (r_w < 32);
    const int iy = 2 * r_w + sy;
    const uint32_t wordoff = (uint32_t)((cp & 3) << 2);
    const uint32_t g0 = (uint32_t)(cp >> 2);

    auto st = [&](int xc, uint32_t hp, uint32_t lp) {
        uint32_t off = (uint32_t)((y * 36 + xc) << 7) + (((g0 ^ (uint32_t)(xc & 7)) << 4)) + wordoff;
        *(uint32_t*)(smem + off) = hp;
        *(uint32_t*)(smem + WBYTES + off) = lp;
    };
    st(0, 0u, 0u); st(33, 0u, 0u); st(34, 0u, 0u); st(35, 0u, 0u);
    if (yok) {
        const float* p0 = in + ((size_t)n * 64 + 2 * cp) * 4096 + iy * 64;
#pragma unroll
        for (int j = 0; j < 16; j++) {
            float4 a4 = *(const float4*)(p0 + 4 * j);
            float4 b4 = *(const float4*)(p0 + 4096 + 4 * j);
            float fa0 = sx ? a4.y : a4.x, fa1 = sx ? a4.w : a4.z;
            float fb0 = sx ? b4.y : b4.x, fb1 = sx ? b4.w : b4.z;
            uint32_t hp, lp;
            split2(fa0, fb0, hp, lp); st(1 + 2 * j, hp, lp);
            split2(fa1, fb1, hp, lp); st(2 + 2 * j, hp, lp);
        }
    } else {
#pragma unroll
        for (int xc = 1; xc <= 32; xc++) st(xc, 0u, 0u);
    }
}

// ---------------- merged weight prep -> FRAGMENT layout ----------------
// layout (u32 units): fi = ((t*(CIN/16)+kall)*(COUT/8) + cog)*32 + lane; value pair:
//   co = cog*8 + (lane>>2); ci(e of pair w) = kall*16 + (lane&3)*2 + w*8 + e
struct WPrepArgs {
    const float* s[12];
    const float* tc1;
    const float* c2;
};
__constant__ struct { int off, size, cout, cin, kk; } c_wseg[12];

__global__ void wprep_all_k(WPrepArgs a, __nv_bfloat16* __restrict__ hi, __nv_bfloat16* __restrict__ lo)
{
    const int O_TC1 = 704512, O_C2 = 835584, TOT = 966656;
    int i = blockIdx.x * 256 + threadIdx.x;
    if (i >= TOT) return;
    float f;
    int cout, cin, kk, j;
    const float* src = nullptr;
    int mode;  // 0=std, 1=tc1, 2=c2
    if (i >= O_C2) { j = i - O_C2; cout = 128; cin = 64; kk = 16; mode = 2; }
    else if (i >= O_TC1) { j = i - O_TC1; cout = 64; cin = 128; kk = 16; mode = 1; }
    else {
        int sidx = 0;
#pragma unroll
        for (int q = 1; q < 12; q++)
            if (i >= c_wseg[q].off) sidx = q;
        j = i - c_wseg[sidx].off;
        cout = c_wseg[sidx].cout; cin = c_wseg[sidx].cin; kk = c_wseg[sidx].kk;
        src = a.s[sidx];
        mode = 0;
    }
    // decompose fragment index
    int e = j & 1;
    int u = j >> 1;
    int w = u & 1;
    int lane = (u >> 1) & 31;
    int v = u >> 6;
    int ncog = cout >> 3;
    int cog = v % ncog; v /= ncog;
    int nk = cin >> 4;
    int kall = v % nk;
    int t = v / nk;
    int co = cog * 8 + (lane >> 2);
    int ci = kall * 16 + (lane & 3) * 2 + w * 8 + e;

    if (mode == 0) {
        f = src[((size_t)co * cin + ci) * kk + t];
    } else if (mode == 1) {
        int pz = t >> 2, jt = t & 3;
        int py = pz >> 1, px = pz & 1, jy = jt >> 1, jx = jt & 1;
        int ky = (1 - py) + 2 * jy, kx = (1 - px) + 2 * jx;
        f = a.tc1[((ci * 64 + co) * 4 + ky) * 4 + kx];
    } else {
        int sg = t >> 2, jt = t & 3;
        int sy = sg >> 1, sx = sg & 1, jy = jt >> 1, jx = jt & 1;
        int ky = 2 * jy + (1 - sy), kx = 2 * jx + (1 - sx);
        f = a.c2[((co * 64 + ci) * 4 + ky) * 4 + kx];
    }
    __nv_bfloat16 h = __float2bfloat16(f);
    hi[i] = h;
    lo[i] = __float2bfloat16(f - __bfloat162float(h));
}

// ---------------- direct-ldmatrix mma conv (R10 partition, frag-B loads) ----------------
template<int CIN, int COUT, int KS, bool RELU_IN, bool RELU_OUT, bool HAS_BIAS, bool ADD_RES>
__global__ void __launch_bounds__(256) mconv2_k(
    const float* __restrict__ in,
    const __nv_bfloat16* __restrict__ whi, const __nv_bfloat16* __restrict__ wlo,
    const float* __restrict__ bias, const float* __restrict__ res,
    float* __restrict__ out)
{
    constexpr int KCH = CIN / 64;
    constexpr int NF  = COUT / 64;
    constexpr int NCOG = COUT / 8;
    constexpr int NK   = CIN / 16;
    extern __shared__ char smem[];
    const uint32_t sH = smem_u32(smem), sL = sH + WBYTES;

    const int tid = threadIdx.x, wid = tid >> 5, lane = tid & 31;
    const int by = blockIdx.x, n = blockIdx.z;
    const int cobase = wid * (COUT / 8);
    const int cogbase = wid * NF;
    const int rowidx = ((lane >> 3) & 1) * 8 + (lane & 7);
    const int khalf = lane >> 4;
    const uint2* Wh2 = (const uint2*)whi;
    const uint2* Wl2 = (const uint2*)wlo;

    float acc[8][NF][4];
#pragma unroll
    for (int m = 0; m < 8; m++)
#pragma unroll
        for (int f = 0; f < NF; f++)
#pragma unroll
            for (int k = 0; k < 4; k++) acc[m][f][k] = 0.f;

    for (int kc = 0; kc < KCH; kc++) {
        if (kc) __syncthreads();
        stage_window<CIN, RELU_IN>(in, n, kc, by, wid, lane, smem);
        __syncthreads();

        for (int t = 0; t < KS * KS; t++) {
            const int dy = (KS == 1) ? 1 : t / KS;
            const int dx = (KS == 1) ? 1 : t % KS;
            const int cx = rowidx + dx;
            const uint32_t cx7 = (uint32_t)(cx & 7);
#pragma unroll
            for (int k16 = 0; k16 < 4; k16++) {
                const int kall = kc * 4 + k16;
                uint32_t bh[NF][2], bl[NF][2];
#pragma unroll
                for (int f = 0; f < NF; f++) {
                    int fi = ((t * NK + kall) * NCOG + cogbase + f) * 32 + lane;
                    uint2 h2 = Wh2[fi], l2 = Wl2[fi];
                    bh[f][0] = h2.x; bh[f][1] = h2.y;
                    bl[f][0] = l2.x; bl[f][1] = l2.y;
                }
                const uint32_t gsw = (((uint32_t)(k16 * 2 + khalf) ^ cx7) << 4);
#pragma unroll
                for (int m = 0; m < 8; m++) {
                    uint32_t off = (uint32_t)((((m >> 1) + dy) * 36 + (m & 1) * 16 + cx) << 7) + gsw;
                    uint32_t ah[4], al[4];
                    ldm4(ah, sH + off);
                    ldm4(al, sL + off);
#pragma unroll
                    for (int f = 0; f < NF; f++) {
                        mma_bf16(acc[m][f], ah, bh[f]);
                        mma_bf16(acc[m][f], ah, bl[f]);
                        mma_bf16(acc[m][f], al, bh[f]);
                    }
                }
            }
        }
    }

    const int r0 = lane >> 2, c0 = (lane & 3) * 2;
#pragma unroll
    for (int m = 0; m < 8; m++)
#pragma unroll
        for (int f = 0; f < NF; f++) {
            int co = cobase + f * 8 + c0;
            int gp = by * 128 + m * 16 + r0;
            float b0v = HAS_BIAS ? bias[co] : 0.f;
            float b1v = HAS_BIAS ? bias[co + 1] : 0.f;
            float v00 = acc[m][f][0] + b0v, v01 = acc[m][f][1] + b1v;
            float v10 = acc[m][f][2] + b0v, v11 = acc[m][f][3] + b1v;
            size_t o0 = ((size_t)n * COUT + co) * 1024 + gp;
            size_t o1 = ((size_t)n * COUT + co + 1) * 1024 + gp;
            if (ADD_RES) {
                v00 += res[o0]; v01 += res[o1];
                v10 += res[o0 + 8]; v11 += res[o1 + 8];
            }
            if (RELU_OUT) {
                v00 = fmaxf(v00, 0.f); v01 = fmaxf(v01, 0.f);
                v10 = fmaxf(v10, 0.f); v11 = fmaxf(v11, 0.f);
            }
            out[o0] = v00; out[o1] = v01;
            out[o0 + 8] = v10; out[o1 + 8] = v11;
        }
}

// ---------------- conv2 as tensor (R10 partition, frag-B) ----------------
__global__ void __launch_bounds__(256) c2m_k(
    const float* __restrict__ in,
    const __nv_bfloat16* __restrict__ whi, const __nv_bfloat16* __restrict__ wlo,
    const float* __restrict__ bias, float* __restrict__ out)
{
    constexpr int COUT = 128, NF = 2, NCOG = 16, NK = 4;
    extern __shared__ char smem[];
    const uint32_t sH = smem_u32(smem), sL = sH + WBYTES;

    const int tid = threadIdx.x, wid = tid >> 5, lane = tid & 31;
    const int by = blockIdx.x, n = blockIdx.z;
    const int cobase = wid * 16;
    const int cogbase = wid * 2;
    const int rowidx = ((lane >> 3) & 1) * 8 + (lane & 7);
    const int khalf = lane >> 4;
    const uint2* Wh2 = (const uint2*)whi;
    const uint2* Wl2 = (const uint2*)wlo;

    float acc[8][NF][4];
#pragma unroll
    for (int m = 0; m < 8; m++)
#pragma unroll
        for (int f = 0; f < NF; f++)
#pragma unroll
            for (int k = 0; k < 4; k++) acc[m][f][k] = 0.f;

    for (int sg = 0; sg < 4; sg++) {
        const int sy = sg >> 1, sx = sg & 1;
        if (sg) __syncthreads();
        stage_window_s2(in, n, by, sy, sx, wid, lane, smem);
        __syncthreads();

        for (int jt = 0; jt < 4; jt++) {
            const int jy = jt >> 1, jx = jt & 1;
            const int dy = jy + 1 - sy;
            const int dx = jx + 1 - sx;
            const int cx = rowidx + dx;
            const uint32_t cx7 = (uint32_t)(cx & 7);
            const int g = sg * 4 + jt;
#pragma unroll
            for (int k16 = 0; k16 < 4; k16++) {
                uint32_t bh[NF][2], bl[NF][2];
#pragma unroll
                for (int f = 0; f < NF; f++) {
                    int fi = ((g * NK + k16) * NCOG + cogbase + f) * 32 + lane;
                    uint2 h2 = Wh2[fi], l2 = Wl2[fi];
                    bh[f][0] = h2.x; bh[f][1] = h2.y;
                    bl[f][0] = l2.x; bl[f][1] = l2.y;
                }
                const uint32_t gsw = (((uint32_t)(k16 * 2 + khalf) ^ cx7) << 4);
#pragma unroll
                for (int m = 0; m < 8; m++) {
                    uint32_t off = (uint32_t)((((m >> 1) + dy) * 36 + (m & 1) * 16 + cx) << 7) + gsw;
                    uint32_t ah[4], al[4];
                    ldm4(ah, sH + off);
                    ldm4(al, sL + off);
#pragma unroll
                    for (int f = 0; f < NF; f++) {
                        mma_bf16(acc[m][f], ah, bh[f]);
                        mma_bf16(acc[m][f], ah, bl[f]);
                        mma_bf16(acc[m][f], al, bh[f]);
                    }
                }
            }
        }
    }

    const int r0 = lane >> 2, c0 = (lane & 3) * 2;
#pragma unroll
    for (int m = 0; m < 8; m++)
#pragma unroll
        for (int f = 0; f < NF; f++) {
            int co = cobase + f * 8 + c0;
            int gp = by * 128 + m * 16 + r0;
            float b0v = bias[co], b1v = bias[co + 1];
            float v00 = fmaxf(acc[m][f][0] + b0v, 0.f);
            float v01 = fmaxf(acc[m][f][1] + b1v, 0.f);
            float v10 = fmaxf(acc[m][f][2] + b0v, 0.f);
            float v11 = fmaxf(acc[m][f][3] + b1v, 0.f);
            size_t o0 = ((size_t)n * COUT + co) * 1024 + gp;
            size_t o1 = ((size_t)n * COUT + co + 1) * 1024 + gp;
            out[o0] = v00; out[o1] = v01;
            out[o0 + 8] = v10; out[o1 + 8] = v11;
        }
}

// ---------------- tc1 as tensor convT (R10 partition, frag-B) ----------------
__global__ void __launch_bounds__(256) tmct_k(
    const float* __restrict__ in,
    const __nv_bfloat16* __restrict__ whi, const __nv_bfloat16* __restrict__ wlo,
    const float* __restrict__ bias, float* __restrict__ out)
{
    constexpr int CIN = 128, NCOG = 8, NK = 8;
    extern __shared__ char smem[];
    const uint32_t sH = smem_u32(smem), sL = sH + WBYTES;

    const int tid = threadIdx.x, wid = tid >> 5, lane = tid & 31;
    const int by = blockIdx.x, pz = blockIdx.y, n = blockIdx.z;
    const int py = pz >> 1, px = pz & 1;
    const int cobase = wid * 8;
    const int rowidx = ((lane >> 3) & 1) * 8 + (lane & 7);
    const int khalf = lane >> 4;
    const uint2* Wh2 = (const uint2*)whi;
    const uint2* Wl2 = (const uint2*)wlo;

    float acc[8][4];
#pragma unroll
    for (int m = 0; m < 8; m++)
#pragma unroll
        for (int k = 0; k < 4; k++) acc[m][k] = 0.f;

    for (int kc = 0; kc < 2; kc++) {
        if (kc) __syncthreads();
        stage_window<CIN, true>(in, n, kc, by, wid, lane, smem);
        __syncthreads();

        for (int jt = 0; jt < 4; jt++) {
            const int jy = jt >> 1, jx = jt & 1;
            const int dy = 1 - jy + py;
            const int dx = 1 - jx + px;
            const int cx = rowidx + dx;
            const uint32_t cx7 = (uint32_t)(cx & 7);
            const int g = pz * 4 + jt;
#pragma unroll
            for (int k16 = 0; k16 < 4; k16++) {
                const int kall = kc * 4 + k16;
                int fi = ((g * NK + kall) * NCOG + wid) * 32 + lane;
                uint2 h2 = Wh2[fi], l2 = Wl2[fi];
                uint32_t bh[2] = {h2.x, h2.y}, bl[2] = {l2.x, l2.y};
                const uint32_t gsw = (((uint32_t)(k16 * 2 + khalf) ^ cx7) << 4);
#pragma unroll
                for (int m = 0; m < 8; m++) {
                    uint32_t off = (uint32_t)((((m >> 1) + dy) * 36 + (m & 1) * 16 + cx) << 7) + gsw;
                    uint32_t ah[4], al[4];
                    ldm4(ah, sH + off);
                    ldm4(al, sL + off);
                    mma_bf16(acc[m], ah, bh);
                    mma_bf16(acc[m], ah, bl);
                    mma_bf16(acc[m], al, bh);
                }
            }
        }
    }

    const int r0 = lane >> 2, c0 = (lane & 3) * 2;
#pragma unroll
    for (int m = 0; m < 8; m++) {
        int p = m * 16 + r0;
        int co = cobase + c0;
        int ga = by * 4 + (p >> 5), gb = p & 31;
        int oy = 2 * ga + py, ox = 2 * gb + px;
        float b0v = bias[co], b1v = bias[co + 1];
        float v00 = fmaxf(acc[m][0] + b0v, 0.f);
        float v01 = fmaxf(acc[m][1] + b1v, 0.f);
        float v10 = fmaxf(acc[m][2] + b0v, 0.f);
        float v11 = fmaxf(acc[m][3] + b1v, 0.f);
        size_t o00 = (((size_t)n * 64 + co) * 64 + oy) * 64 + ox;
        out[o00] = v00; out[o00 + 4096] = v01;
        out[o00 + 16] = v10; out[o00 + 4096 + 16] = v11;
    }
}

// ---------------- f32x2 helpers ----------------
__device__ __forceinline__ unsigned long long pk2(float a, float b) {
    unsigned long long r;
    asm("mov.b64 %0, {%1, %2};" : "=l"(r) : "f"(a), "f"(b));
    return r;
}
__device__ __forceinline__ void fma2(unsigned long long& d, unsigned long long a, unsigned long long b) {
    asm("fma.rn.f32x2 %0, %1, %2, %0;" : "+l"(d) : "l"(a), "l"(b));
}
__device__ __forceinline__ float2 upk2(unsigned long long a) {
    float2 f;
    asm("mov.b64 {%0, %1}, %2;" : "=f"(f.x), "=f"(f.y) : "l"(a));
    return f;
}

// ---------------- generic direct conv (conv1 only) ----------------
template<int CIN, int COUT, int KS, int STR, int PAD, int IH, int IW, int CO_BLK, int PX,
         bool RELU_OUT>
__global__ void __launch_bounds__(256) conv_k(
    const float* __restrict__ in, const float* __restrict__ w,
    const float* __restrict__ bias, float* __restrict__ out)
{
    constexpr int OH = (IH + 2 * PAD - KS) / STR + 1;
    constexpr int OW = (IW + 2 * PAD - KS) / STR + 1;
    constexpr int KK = KS * KS;
    constexpr int COLS = STR * (PX - 1) + KS;
    extern __shared__ float sw[];

    const int n = blockIdx.z, co0 = blockIdx.y * CO_BLK, tid = threadIdx.x;
    for (int i = tid; i < CIN * KK * CO_BLK; i += blockDim.x) {
        int co = i % CO_BLK, t = (i / CO_BLK) % KK, ci = i / (CO_BLK * KK);
        sw[i] = w[((size_t)(co0 + co) * CIN + ci) * KK + t];
    }
    __syncthreads();

    int p0 = (blockIdx.x * blockDim.x + tid) * PX;
    if (p0 >= OH * OW) return;
    int oy = p0 / OW, ox0 = p0 % OW;
    int iy0 = oy * STR - PAD, ix0 = ox0 * STR - PAD;

    bool rok[KS]; int roff[KS];
#pragma unroll
    for (int ky = 0; ky < KS; ky++) {
        int y = iy0 + ky; rok[ky] = (y >= 0) && (y < IH); roff[ky] = y * IW;
    }
    bool cok[COLS]; int coff[COLS];
#pragma unroll
    for (int cx = 0; cx < COLS; cx++) {
        int x = ix0 + cx; cok[cx] = (x >= 0) && (x < IW); coff[cx] = x;
    }

    unsigned long long acc[PX][CO_BLK / 2];
#pragma unroll
    for (int px = 0; px < PX; px++)
#pragma unroll
        for (int j = 0; j < CO_BLK / 2; j++) acc[px][j] = 0ull;

    const float* inb = in + (size_t)n * CIN * IH * IW;
    for (int ci = 0; ci < CIN; ci++) {
        const float* inc = inb + (size_t)ci * IH * IW;
        const ulonglong2* wt = (const ulonglong2*)(sw + (size_t)ci * KK * CO_BLK);
#pragma unroll
        for (int ky = 0; ky < KS; ky++) {
            unsigned long long pv[COLS];
#pragma unroll
            for (int cx = 0; cx < COLS; cx++) {
                float val = (rok[ky] && cok[cx]) ? inc[roff[ky] + coff[cx]] : 0.f;
                pv[cx] = pk2(val, val);
            }
#pragma unroll
            for (int kx = 0; kx < KS; kx++) {
                const int t = ky * KS + kx;
#pragma unroll
                for (int q = 0; q < CO_BLK / 4; q++) {
                    ulonglong2 ww = wt[t * (CO_BLK / 4) + q];
#pragma unroll
                    for (int px = 0; px < PX; px++) {
                        fma2(acc[px][2 * q + 0], pv[px * STR + kx], ww.x);
                        fma2(acc[px][2 * q + 1], pv[px * STR + kx], ww.y);
                    }
                }
            }
        }
    }

    float* ob = out + ((size_t)n * COUT + co0) * OH * OW + p0;
#pragma unroll
    for (int j = 0; j < CO_BLK / 2; j++) {
        float b0 = bias[co0 + 2 * j], b1 = bias[co0 + 2 * j + 1];
        float r0[PX], r1[PX];
#pragma unroll
        for (int px = 0; px < PX; px++) {
            float2 f = upk2(acc[px][j]);
            r0[px] = f.x + b0; r1[px] = f.y + b1;
            if (RELU_OUT) { r0[px] = fmaxf(r0[px], 0.f); r1[px] = fmaxf(r1[px], 0.f); }
        }
        float* o0 = ob + (size_t)(2 * j + 0) * OH * OW;
        float* o1 = ob + (size_t)(2 * j + 1) * OH * OW;
        if (PX == 2) {
            *(float2*)o0 = make_float2(r0[0], r0[1 % PX]);
            *(float2*)o1 = make_float2(r1[0], r1[1 % PX]);
        } else {
#pragma unroll
            for (int px = 0; px < PX; px++) { o0[px] = r0[px]; o1[px] = r1[px]; }
        }
    }
}

// ---------------- transposed conv k=4 s=2 p=1 (gather) — tc2 only ----------------
template<int CIN, int COUT, int IH, int IW, int CO_BLK, int PX,
         bool RELU_IN, bool RELU_OUT>
__global__ void __launch_bounds__(256) convt_k(
    const float* __restrict__ in, const float* __restrict__ w,
    const float* __restrict__ bias, float* __restrict__ out)
{
    constexpr int OH = IH * 2, OW = IW * 2;
    extern __shared__ float sw[];

    const int n = blockIdx.z, co0 = blockIdx.y * CO_BLK, tid = threadIdx.x;
    for (int i = tid; i < CIN * 16 * CO_BLK; i += blockDim.x) {
        int co = i % CO_BLK, t = (i / CO_BLK) % 16, ci = i / (CO_BLK * 16);
        sw[i] = (co0 + co < COUT) ? w[((size_t)ci * COUT + (co0 + co)) * 16 + t] : 0.f;
    }
    __syncthreads();

    int p0 = (blockIdx.x * blockDim.x + tid) * PX;
    if (p0 >= OH * OW) return;
    int oy = p0 / OW, ox0 = p0 % OW;
    const int kpy = (oy + 1) & 1, kp0 = (ox0 + 1) & 1;

    int iy[2]; bool vy[2];
#pragma unroll
    for (int a = 0; a < 2; a++) {
        int ky = kpy + 2 * a, yy = oy + 1 - ky;
        iy[a] = yy >> 1; vy[a] = (yy >= 0) && (iy[a] < IH);
    }
    int ixp[PX][2]; bool vxp[PX][2];
#pragma unroll
    for (int px = 0; px < PX; px++) {
        int kpx = (kp0 + px) & 1;
#pragma unroll
        for (int b = 0; b < 2; b++) {
            int kx = kpx + 2 * b, xx = ox0 + px + 1 - kx;
            ixp[px][b] = xx >> 1; vxp[px][b] = (xx >= 0) && (ixp[px][b] < IW);
        }
    }

    unsigned long long acc[PX][CO_BLK / 2];
#pragma unroll
    for (int px = 0; px < PX; px++)
#pragma unroll
        for (int j = 0; j < CO_BLK / 2; j++) acc[px][j] = 0ull;

    const float* inb = in + (size_t)n * CIN * IH * IW;
    for (int ci = 0; ci < CIN; ci++) {
        const float* inc = inb + (size_t)ci * IH * IW;
        unsigned long long pv[PX][4];
#pragma unroll
        for (int px = 0; px < PX; px++)
#pragma unroll
            for (int a = 0; a < 2; a++)
#pragma unroll
                for (int b = 0; b < 2; b++) {
                    float val = 0.f;
                    if (vy[a] && vxp[px][b]) val = inc[iy[a] * IW + ixp[px][b]];
                    if (RELU_IN) val = fmaxf(val, 0.f);
                    pv[px][a * 2 + b] = pk2(val, val);
                }
        const ulonglong2* wt = (const ulonglong2*)(sw + (size_t)ci * 16 * CO_BLK);
#pragma unroll
        for (int g = 0; g < 2; g++) {
            const int kpxg = (kp0 + g) & 1;
#pragma unroll
            for (int a = 0; a < 2; a++)
#pragma unroll
                for (int b = 0; b < 2; b++) {
                    const int t = (kpy + 2 * a) * 4 + (kpxg + 2 * b);
#pragma unroll
                    for (int q = 0; q < CO_BLK / 4; q++) {
                        ulonglong2 ww = wt[t * (CO_BLK / 4) + q];
#pragma unroll
                        for (int px = g; px < PX; px += 2) {
                            fma2(acc[px][2 * q + 0], pv[px][a * 2 + b], ww.x);
                            fma2(acc[px][2 * q + 1], pv[px][a * 2 + b], ww.y);
                        }
                    }
                }
        }
    }

    float* ob = out + ((size_t)n * COUT + co0) * OH * OW + p0;
#pragma unroll
    for (int j = 0; j < CO_BLK / 2; j++) {
        float b0 = (co0 + 2 * j < COUT) ? bias[co0 + 2 * j] : 0.f;
        float b1 = (co0 + 2 * j + 1 < COUT) ? bias[co0 + 2 * j + 1] : 0.f;
        float r0[PX], r1[PX];
#pragma unroll
        for (int px = 0; px < PX; px++) {
            float2 f = upk2(acc[px][j]);
            r0[px] = f.x + b0; r1[px] = f.y + b1;
            if (RELU_OUT) { r0[px] = fmaxf(r0[px], 0.f); r1[px] = fmaxf(r1[px], 0.f); }
        }
        float* o0 = ob + (size_t)(2 * j + 0) * OH * OW;
        float* o1 = ob + (size_t)(2 * j + 1) * OH * OW;
#pragma unroll
        for (int px = 0; px < PX; px++) {
            if (co0 + 2 * j + 0 < COUT) o0[px] = r0[px];
            if (co0 + 2 * j + 1 < COUT) o1[px] = r1[px];
        }
    }
}

// ---------------- VQ ----------------
__global__ void vq_init_k(const float* __restrict__ E, float* __restrict__ enorm,
                          float* __restrict__ counts, float* __restrict__ sqsum)
{
    int k = blockIdx.x * blockDim.x + threadIdx.x;
    if (k < KCODES) {
        float s = 0.f;
#pragma unroll
        for (int d = 0; d < DDIM; d++) { float e = E[k * DDIM + d]; s += e * e; }
        enorm[k] = s; counts[k] = 0.f;
    }
    if (k == 0) sqsum[0] = 0.f;
}

__global__ void vq_k(const float* __restrict__ ze, const float* __restrict__ E,
                     const float* __restrict__ enorm, float* __restrict__ zq,
                     float* __restrict__ counts, float* __restrict__ sqsum)
{
    __shared__ float sE[128 * DDIM];
    __shared__ float sN[128];
    __shared__ float sred[8];

    const int tid = threadIdx.x;
    const int r = blockIdx.x * blockDim.x + tid;
    const int n = r >> 10, hw = r & 1023;

    const float* zb = ze + (size_t)n * DDIM * 1024 + hw;
    float z[DDIM];
#pragma unroll
    for (int d = 0; d < DDIM; d++) z[d] = zb[(size_t)d * 1024];
    float zn = 0.f;
#pragma unroll
    for (int d = 0; d < DDIM; d++) zn += z[d] * z[d];

    float best = 3.4e38f; int bidx = 0;
    for (int c = 0; c < KCODES / 128; c++) {
        __syncthreads();
        for (int i = tid; i < 128 * DDIM; i += blockDim.x) sE[i] = E[c * 128 * DDIM + i];
        for (int i = tid; i < 128; i += blockDim.x) sN[i] = enorm[c * 128 + i];
        __syncthreads();
        for (int k = 0; k < 128; k++) {
            const float4* e4 = (const float4*)(sE + k * DDIM);
            float a0 = 0.f, a1 = 0.f, a2 = 0.f, a3 = 0.f;
#pragma unroll
            for (int m = 0; m < DDIM / 4; m++) {
                float4 e = e4[m];
                a0 += z[4 * m + 0] * e.x; a1 += z[4 * m + 1] * e.y;
                a2 += z[4 * m + 2] * e.z; a3 += z[4 * m + 3] * e.w;
            }
            float dist = zn + sN[k] - 2.f * ((a0 + a1) + (a2 + a3));
            if (dist < best) { best = dist; bidx = c * 128 + k; }
        }
    }

    float local = 0.f;
    const float* eb = E + (size_t)bidx * DDIM;
    float* zqb = zq + (size_t)n * DDIM * 1024 + hw;
#pragma unroll
    for (int d = 0; d < DDIM; d++) {
        float e = eb[d];
        zqb[(size_t)d * 1024] = e;
        float df = e - z[d];
        local += df * df;
    }
    atomicAdd(&counts[bidx], 1.f);
#pragma unroll
    for (int o = 16; o; o >>= 1) local += __shfl_down_sync(0xffffffffu, local, o);
    if ((tid & 31) == 0) sred[tid >> 5] = local;
    __syncthreads();
    if (tid < 8) {
        local = sred[tid];
#pragma unroll
        for (int o = 4; o; o >>= 1) local += __shfl_down_sync(0xffu, local, o);
        if (tid == 0) atomicAdd(sqsum, local);
    }
}

__global__ void finalize_k(const float* __restrict__ counts, const float* __restrict__ sqsum,
                           float* __restrict__ out)
{
    __shared__ float sred[16];
    int tid = threadIdx.x;
    float p = counts[tid] * (1.f / 65536.f);
    float term = -p * log2f(p + 1e-10f);
#pragma unroll
    for (int o = 16; o; o >>= 1) term += __shfl_down_sync(0xffffffffu, term, o);
    if ((tid & 31) == 0) sred[tid >> 5] = term;
    __syncthreads();
    if (tid < 16) {
        term = sred[tid];
#pragma unroll
        for (int o = 8; o; o >>= 1) term += __shfl_down_sync(0xffffu, term, o);
        if (tid == 0) {
            float mse = sqsum[0] / (65536.f * 64.f);
            const int base = 1 + BATCH * 3 * 128 * 128;
            out[0] = 1.25f * mse;
            out[base + 0] = mse;
            out[base + 1] = mse;
            out[base + 2] = exp2f(term);
        }
    }
}

// ---------------- launch ----------------
extern "C" void kernel_launch(void* const* d_in, const int* in_sizes, int n_in,
                              void* d_out, int out_size)
{
    const float* x        = (const float*)d_in[0];
    const float* enc_w1   = (const float*)d_in[1];
    const float* enc_b1   = (const float*)d_in[2];
    const float* enc_w2   = (const float*)d_in[3];
    const float* enc_b2   = (const float*)d_in[4];
    const float* enc_w3   = (const float*)d_in[5];
    const float* enc_b3   = (const float*)d_in[6];
    const float* enc_w4   = (const float*)d_in[7];
    const float* enc_b4   = (const float*)d_in[8];
    const float* enc_rw1  = (const float*)d_in[9];
    const float* enc_rw2  = (const float*)d_in[10];
    const float* enc_adjw = (const float*)d_in[11];
    const float* enc_adjb = (const float*)d_in[12];
    const float* E        = (const float*)d_in[13];
    const float* dec_adjw = (const float*)d_in[14];
    const float* dec_adjb = (const float*)d_in[15];
    const float* dec_rw1  = (const float*)d_in[16];
    const float* dec_rw2  = (const float*)d_in[17];
    const float* tc1_w    = (const float*)d_in[18];
    const float* tc1_b    = (const float*)d_in[19];
    const float* tc2_w    = (const float*)d_in[20];
    const float* tc2_b    = (const float*)d_in[21];

    float* out   = (float*)d_out;
    float* recon = out + 1;

    float *h1, *a, *b, *mid, *ze, *zq, *enorm, *counts, *sqsum;
    __nv_bfloat16 *whi, *wlo;
    cudaGetSymbolAddress((void**)&h1, d_h1);
    cudaGetSymbolAddress((void**)&a, d_a);
    cudaGetSymbolAddress((void**)&b, d_b);
    cudaGetSymbolAddress((void**)&mid, d_mid);
    cudaGetSymbolAddress((void**)&ze, d_ze);
    cudaGetSymbolAddress((void**)&zq, d_zq);
    cudaGetSymbolAddress((void**)&enorm, d_enorm);
    cudaGetSymbolAddress((void**)&counts, d_counts);
    cudaGetSymbolAddress((void**)&sqsum, d_sqsum);
    cudaGetSymbolAddress((void**)&whi, d_whi);
    cudaGetSymbolAddress((void**)&wlo, d_wlo);

    const size_t O_W3 = 0, O_W4 = 147456, O_R1E0 = 294912, O_R1E1 = 368640;
    const size_t O_R2E0 = 442368, O_R2E1 = 450560, O_ADJ = 458752, O_DADJ = 466944;
    const size_t O_R1D0 = 540672, O_R1D1 = 614400, O_R2D0 = 688128, O_R2D1 = 696320;
    const size_t O_TC1 = 704512, O_C2 = 835584;

    {
        static const struct { int off, size, cout, cin, kk; } segs[12] = {
            {0, 147456, 128, 128, 9}, {147456, 147456, 128, 128, 9},
            {294912, 73728, 64, 128, 9}, {368640, 73728, 64, 128, 9},
            {442368, 8192, 128, 64, 1}, {450560, 8192, 128, 64, 1},
            {458752, 8192, 64, 128, 1}, {466944, 73728, 128, 64, 9},
            {540672, 73728, 64, 128, 9}, {614400, 73728, 64, 128, 9},
            {688128, 8192, 128, 64, 1}, {696320, 8192, 128, 64, 1}};
        cudaMemcpyToSymbolAsync(c_wseg, segs, sizeof(segs), 0, cudaMemcpyHostToDevice);
    }
    WPrepArgs wa;
    wa.s[0] = enc_w3; wa.s[1] = enc_w4;
    wa.s[2] = enc_rw1; wa.s[3] = enc_rw1 + 64 * 128 * 9;
    wa.s[4] = enc_rw2; wa.s[5] = enc_rw2 + 128 * 64;
    wa.s[6] = enc_adjw; wa.s[7] = dec_adjw;
    wa.s[8] = dec_rw1; wa.s[9] = dec_rw1 + 64 * 128 * 9;
    wa.s[10] = dec_rw2; wa.s[11] = dec_rw2 + 128 * 64;
    wa.tc1 = tc1_w; wa.c2 = enc_w2;
    wprep_all_k<<<(966656 + 255) / 256, 256>>>(wa, whi, wlo);

    const int TPB = 256;
    const dim3 TG(8, 1, BATCH);

    conv_k<3, 64, 4, 2, 1, 128, 128, 16, 2, true>
        <<<dim3(4096 / (TPB * 2), 4, BATCH), TPB, 3 * 16 * 16 * 4>>>(x, enc_w1, enc_b1, h1);

    auto t3_128_relu = mconv2_k<128, 128, 3, false, true, true, false>;
    auto t3_128      = mconv2_k<128, 128, 3, false, false, true, false>;
    auto t3_r1       = mconv2_k<128, 64, 3, true, false, false, false>;
    auto t1_r2       = mconv2_k<64, 128, 1, true, false, false, true>;
    auto t1_adj      = mconv2_k<128, 64, 1, true, false, true, false>;
    auto t3_dadj     = mconv2_k<64, 128, 3, false, false, true, false>;
    cudaFuncSetAttribute((const void*)t3_128_relu, cudaFuncAttributeMaxDynamicSharedMemorySize, MC_SMEM);
    cudaFuncSetAttribute((const void*)t3_128, cudaFuncAttributeMaxDynamicSharedMemorySize, MC_SMEM);
    cudaFuncSetAttribute((const void*)t3_r1, cudaFuncAttributeMaxDynamicSharedMemorySize, MC_SMEM);
    cudaFuncSetAttribute((const void*)t1_r2, cudaFuncAttributeMaxDynamicSharedMemorySize, MC_SMEM);
    cudaFuncSetAttribute((const void*)t1_adj, cudaFuncAttributeMaxDynamicSharedMemorySize, MC_SMEM);
    cudaFuncSetAttribute((const void*)t3_dadj, cudaFuncAttributeMaxDynamicSharedMemorySize, MC_SMEM);
    cudaFuncSetAttribute((const void*)tmct_k, cudaFuncAttributeMaxDynamicSharedMemorySize, MC_SMEM);
    cudaFuncSetAttribute((const void*)c2m_k, cudaFuncAttributeMaxDynamicSharedMemorySize, MC_SMEM);

    c2m_k<<<TG, TPB, MC_SMEM>>>(h1, whi + O_C2, wlo + O_C2, enc_b2, a);

    t3_128_relu<<<TG, TPB, MC_SMEM>>>(a, whi + O_W3, wlo + O_W3, enc_b3, nullptr, b);
    t3_128<<<TG, TPB, MC_SMEM>>>(b, whi + O_W4, wlo + O_W4, enc_b4, nullptr, a);
    t3_r1<<<TG, TPB, MC_SMEM>>>(a, whi + O_R1E0, wlo + O_R1E0, nullptr, nullptr, mid);
    t1_r2<<<TG, TPB, MC_SMEM>>>(mid, whi + O_R2E0, wlo + O_R2E0, nullptr, a, a);
    t3_r1<<<TG, TPB, MC_SMEM>>>(a, whi + O_R1E1, wlo + O_R1E1, nullptr, nullptr, mid);
    t1_r2<<<TG, TPB, MC_SMEM>>>(mid, whi + O_R2E1, wlo + O_R2E1, nullptr, a, a);
    t1_adj<<<TG, TPB, MC_SMEM>>>(a, whi + O_ADJ, wlo + O_ADJ, enc_adjb, nullptr, ze);

    vq_init_k<<<2, 256>>>(E, enorm, counts, sqsum);
    vq_k<<<65536 / 256, 256>>>(ze, E, enorm, zq, counts, sqsum);

    t3_dadj<<<TG, TPB, MC_SMEM>>>(zq, whi + O_DADJ, wlo + O_DADJ, dec_adjb, nullptr, a);
    t3_r1<<<TG, TPB, MC_SMEM>>>(a, whi + O_R1D0, wlo + O_R1D0, nullptr, nullptr, mid);
    t1_r2<<<TG, TPB, MC_SMEM>>>(mid, whi + O_R2D0, wlo + O_R2D0, nullptr, a, a);
    t3_r1<<<TG, TPB, MC_SMEM>>>(a, whi + O_R1D1, wlo + O_R1D1, nullptr, nullptr, mid);
    t1_r2<<<TG, TPB, MC_SMEM>>>(mid, whi + O_R2D1, wlo + O_R2D1, nullptr, a, a);

    tmct_k<<<dim3(8, 4, BATCH), TPB, MC_SMEM>>>(a, whi + O_TC1, wlo + O_TC1, tc1_b, h1);
    convt_k<64, 3, 64, 64, 4, 4, false, false>
        <<<dim3(16384 / (TPB * 4), 1, BATCH), TPB, 64 * 16 * 4 * 4>>>(h1, tc2_w, tc2_b, recon);

    finalize_k<<<1, 512>>>(counts, sqsum, out);
}

// round 14
// speedup vs baseline: 1.5521x; 1.1139x over previous
#include <cuda_runtime.h>
#include <cuda_bf16.h>
#include <math.h>
#include <stdint.h>

#define BATCH 64
#define KCODES 512
#define DDIM 64

__device__ float d_h1 [BATCH * 64 * 64 * 64];
__device__ float d_a  [BATCH * 128 * 32 * 32];
__device__ float d_b  [BATCH * 128 * 32 * 32];
__device__ float d_mid[BATCH * 64 * 32 * 32];
__device__ float d_ze [BATCH * 64 * 32 * 32];
__device__ float d_zq [BATCH * 64 * 32 * 32];
__device__ float d_enorm [KCODES];
__device__ float d_counts[KCODES];
__device__ float d_sqsum[1];
__device__ __nv_bfloat16 d_whi[1 << 20];
__device__ __nv_bfloat16 d_wlo[1 << 20];

__device__ __forceinline__ uint32_t smem_u32(const void* p) {
    uint32_t a;
    asm("{ .reg .u64 t; cvta.to.shared.u64 t, %1; cvt.u32.u64 %0, t; }" : "=r"(a) : "l"(p));
    return a;
}
__device__ __forceinline__ void mma_bf16(float* c, const uint32_t* a, const uint32_t* b) {
    asm volatile(
        "mma.sync.aligned.m16n8k16.row.col.f32.bf16.bf16.f32 "
        "{%0,%1,%2,%3}, {%4,%5,%6,%7}, {%8,%9}, {%0,%1,%2,%3};"
        : "+f"(c[0]), "+f"(c[1]), "+f"(c[2]), "+f"(c[3])
        : "r"(a[0]), "r"(a[1]), "r"(a[2]), "r"(a[3]), "r"(b[0]), "r"(b[1]));
}
__device__ __forceinline__ void ldm4(uint32_t* a, uint32_t addr) {
    asm volatile("ldmatrix.sync.aligned.m8n8.x4.shared.b16 {%0,%1,%2,%3}, [%4];"
                 : "=r"(a[0]), "=r"(a[1]), "=r"(a[2]), "=r"(a[3]) : "r"(addr));
}
__device__ __forceinline__ void split2(float f0, float f1, uint32_t& hp, uint32_t& lp) {
    asm("cvt.rn.bf16x2.f32 %0, %1, %2;" : "=r"(hp) : "f"(f1), "f"(f0));
    float h0 = __uint_as_float(hp << 16);
    float h1 = __uint_as_float(hp & 0xffff0000u);
    asm("cvt.rn.bf16x2.f32 %0, %1, %2;" : "=r"(lp) : "f"(f1 - h1), "f"(f0 - h0));
}
__device__ __forceinline__ unsigned long long pk2(float a, float b) {
    unsigned long long r;
    asm("mov.b64 %0, {%1, %2};" : "=l"(r) : "f"(a), "f"(b));
    return r;
}
__device__ __forceinline__ void fma2(unsigned long long& d, unsigned long long a, unsigned long long b) {
    asm("fma.rn.f32x2 %0, %1, %2, %0;" : "+l"(d) : "l"(a), "l"(b));
}
__device__ __forceinline__ float2 upk2(unsigned long long a) {
    float2 f;
    asm("mov.b64 {%0, %1}, %2;" : "=f"(f.x), "=f"(f.y) : "l"(a));
    return f;
}

// window: [6 rows][36 cols][64 ci] bf16, 128B/(row,col), granule(16B) XOR-swizzled by col&7
static constexpr int WBYTES = 6 * 36 * 128;   // 27648
static constexpr int MC_SMEM = 2 * WBYTES;    // 55296

template<int CIN, bool RELU_IN>
__device__ __forceinline__ void stage_window(const float* __restrict__ in,
                                             int n, int kc, int by,
                                             int wid, int lane, char* smem)
{
    if (wid >= 6) return;
    const int y = wid, cp = lane;
    const int y_in = by * 4 + y - 1;
    const bool yok = (y_in >= 0) && (y_in < 32);
    const uint32_t wordoff = (uint32_t)((cp & 3) << 2);
    const uint32_t g0 = (uint32_t)(cp >> 2);

    auto st = [&](int xc, uint32_t hp, uint32_t lp) {
        uint32_t off = (uint32_t)((y * 36 + xc) << 7) + (((g0 ^ (uint32_t)(xc & 7)) << 4)) + wordoff;
        *(uint32_t*)(smem + off) = hp;
        *(uint32_t*)(smem + WBYTES + off) = lp;
    };
    st(0, 0u, 0u); st(33, 0u, 0u); st(34, 0u, 0u); st(35, 0u, 0u);
    if (yok) {
        const float* p0 = in + ((size_t)n * CIN + kc * 64 + 2 * cp) * 1024 + y_in * 32;
#pragma unroll
        for (int j = 0; j < 8; j++) {
            float4 a4 = *(const float4*)(p0 + 4 * j);
            float4 b4 = *(const float4*)(p0 + 1024 + 4 * j);
            if (RELU_IN) {
                a4.x = fmaxf(a4.x, 0.f); a4.y = fmaxf(a4.y, 0.f);
                a4.z = fmaxf(a4.z, 0.f); a4.w = fmaxf(a4.w, 0.f);
                b4.x = fmaxf(b4.x, 0.f); b4.y = fmaxf(b4.y, 0.f);
                b4.z = fmaxf(b4.z, 0.f); b4.w = fmaxf(b4.w, 0.f);
            }
            float fa[4] = {a4.x, a4.y, a4.z, a4.w};
            float fb[4] = {b4.x, b4.y, b4.z, b4.w};
#pragma unroll
            for (int e = 0; e < 4; e++) {
                uint32_t hp, lp;
                split2(fa[e], fb[e], hp, lp);
                st(1 + 4 * j + e, hp, lp);
            }
        }
    } else {
#pragma unroll
        for (int xc = 1; xc <= 32; xc++) st(xc, 0u, 0u);
    }
}

__device__ __forceinline__ void stage_window_s2(const float* __restrict__ in,
                                                int n, int by, int sy, int sx,
                                                int wid, int lane, char* smem)
{
    if (wid >= 6) return;
    const int y = wid, cp = lane;
    const int r_w = by * 4 + y - 1;
    const bool yok = (r_w >= 0) && (r_w < 32);
    const int iy = 2 * r_w + sy;
    const uint32_t wordoff = (uint32_t)((cp & 3) << 2);
    const uint32_t g0 = (uint32_t)(cp >> 2);

    auto st = [&](int xc, uint32_t hp, uint32_t lp) {
        uint32_t off = (uint32_t)((y * 36 + xc) << 7) + (((g0 ^ (uint32_t)(xc & 7)) << 4)) + wordoff;
        *(uint32_t*)(smem + off) = hp;
        *(uint32_t*)(smem + WBYTES + off) = lp;
    };
    st(0, 0u, 0u); st(33, 0u, 0u); st(34, 0u, 0u); st(35, 0u, 0u);
    if (yok) {
        const float* p0 = in + ((size_t)n * 64 + 2 * cp) * 4096 + iy * 64;
#pragma unroll
        for (int j = 0; j < 16; j++) {
            float4 a4 = *(const float4*)(p0 + 4 * j);
            float4 b4 = *(const float4*)(p0 + 4096 + 4 * j);
            float fa0 = sx ? a4.y : a4.x, fa1 = sx ? a4.w : a4.z;
            float fb0 = sx ? b4.y : b4.x, fb1 = sx ? b4.w : b4.z;
            uint32_t hp, lp;
            split2(fa0, fb0, hp, lp); st(1 + 2 * j, hp, lp);
            split2(fa1, fb1, hp, lp); st(2 + 2 * j, hp, lp);
        }
    } else {
#pragma unroll
        for (int xc = 1; xc <= 32; xc++) st(xc, 0u, 0u);
    }
}

// ---------------- merged weight prep -> FRAGMENT layout ----------------
// fi = ((t*(CIN/16)+kall)*(COUT/8) + cog)*32 + lane;
//   co = cog*8 + (lane>>2); ci(e of pair w) = kall*16 + (lane&3)*2 + w*8 + e
struct WPrepArgs {
    const float* s[12];
    const float* tc1;
    const float* c2;
};
__constant__ struct { int off, size, cout, cin, kk; } c_wseg[12];

__global__ void wprep_all_k(WPrepArgs a, __nv_bfloat16* __restrict__ hi, __nv_bfloat16* __restrict__ lo)
{
    const int O_TC1 = 704512, O_C2 = 835584, TOT = 966656;
    int i = blockIdx.x * 256 + threadIdx.x;
    if (i >= TOT) return;
    float f;
    int cout, cin, j;
    const float* src = nullptr;
    int mode;
    if (i >= O_C2) { j = i - O_C2; cout = 128; cin = 64; mode = 2; }
    else if (i >= O_TC1) { j = i - O_TC1; cout = 64; cin = 128; mode = 1; }
    else {
        int sidx = 0;
#pragma unroll
        for (int q = 1; q < 12; q++)
            if (i >= c_wseg[q].off) sidx = q;
        j = i - c_wseg[sidx].off;
        cout = c_wseg[sidx].cout; cin = c_wseg[sidx].cin;
        src = a.s[sidx];
        mode = 0;
    }
    int e = j & 1;
    int u = j >> 1;
    int w = u & 1;
    int lane = (u >> 1) & 31;
    int v = u >> 6;
    int ncog = cout >> 3;
    int cog = v % ncog; v /= ncog;
    int nk = cin >> 4;
    int kall = v % nk;
    int t = v / nk;
    int co = cog * 8 + (lane >> 2);
    int ci = kall * 16 + (lane & 3) * 2 + w * 8 + e;

    if (mode == 0) {
        int kk = c_wseg[0].kk;  // placeholder; recompute below
        // need kk of this segment: find again (cheap)
        int sidx = 0;
#pragma unroll
        for (int q = 1; q < 12; q++)
            if (i >= c_wseg[q].off) sidx = q;
        kk = c_wseg[sidx].kk;
        f = src[((size_t)co * cin + ci) * kk + t];
    } else if (mode == 1) {
        int pz = t >> 2, jt = t & 3;
        int py = pz >> 1, px = pz & 1, jy = jt >> 1, jx = jt & 1;
        int ky = (1 - py) + 2 * jy, kx = (1 - px) + 2 * jx;
        f = a.tc1[((ci * 64 + co) * 4 + ky) * 4 + kx];
    } else {
        int sg = t >> 2, jt = t & 3;
        int sy = sg >> 1, sx = sg & 1, jy = jt >> 1, jx = jt & 1;
        int ky = 2 * jy + (1 - sy), kx = 2 * jx + (1 - sx);
        f = a.c2[((co * 64 + ci) * 4 + ky) * 4 + kx];
    }
    __nv_bfloat16 h = __float2bfloat16(f);
    hi[i] = h;
    lo[i] = __float2bfloat16(f - __bfloat162float(h));
}

// ---------------- mma conv: warp tile = MT m-tiles x 32 co, frag-B ----------------
template<int CIN, int COUT, int KS, bool RELU_IN, bool RELU_OUT, bool HAS_BIAS, bool ADD_RES>
__global__ void __launch_bounds__(256, 2) mconv2_k(
    const float* __restrict__ in,
    const __nv_bfloat16* __restrict__ whi, const __nv_bfloat16* __restrict__ wlo,
    const float* __restrict__ bias, const float* __restrict__ res,
    float* __restrict__ out)
{
    constexpr int KCH = CIN / 64;
    constexpr int CW = COUT / 32;
    constexpr int MT = CW;
    constexpr int NF = 4;
    constexpr int NCOG = COUT / 8;
    constexpr int NK = CIN / 16;
    extern __shared__ char smem[];
    const uint32_t sH = smem_u32(smem), sL = sH + WBYTES;

    const int tid = threadIdx.x, wid = tid >> 5, lane = tid & 31;
    const int by = blockIdx.x, n = blockIdx.z;
    const int mg = wid / CW, cg = wid % CW;
    const int cobase = cg * 32;
    const int cogbase = cg * 4;
    const int rowidx = ((lane >> 3) & 1) * 8 + (lane & 7);
    const int khalf = lane >> 4;
    const uint2* Wh2 = (const uint2*)whi;
    const uint2* Wl2 = (const uint2*)wlo;

    float acc[MT][NF][4];
#pragma unroll
    for (int m = 0; m < MT; m++)
#pragma unroll
        for (int f = 0; f < NF; f++)
#pragma unroll
            for (int k = 0; k < 4; k++) acc[m][f][k] = 0.f;

    for (int kc = 0; kc < KCH; kc++) {
        if (kc) __syncthreads();
        stage_window<CIN, RELU_IN>(in, n, kc, by, wid, lane, smem);
        __syncthreads();

        for (int t = 0; t < KS * KS; t++) {
            const int dy = (KS == 1) ? 1 : t / KS;
            const int dx = (KS == 1) ? 1 : t % KS;
            const int cx = rowidx + dx;
            const uint32_t cx7 = (uint32_t)(cx & 7);
#pragma unroll
            for (int k16 = 0; k16 < 4; k16++) {
                const int kall = kc * 4 + k16;
                const uint32_t gsw = (((uint32_t)(k16 * 2 + khalf) ^ cx7) << 4);
                uint32_t ah[MT][4], al[MT][4];
#pragma unroll
                for (int m = 0; m < MT; m++) {
                    const int mm = mg * MT + m;
                    uint32_t off = (uint32_t)((((mm >> 1) + dy) * 36 + (mm & 1) * 16 + cx) << 7) + gsw;
                    ldm4(ah[m], sH + off);
                    ldm4(al[m], sL + off);
                }
#pragma unroll
                for (int f = 0; f < NF; f++) {
                    int fi = ((t * NK + kall) * NCOG + cogbase + f) * 32 + lane;
                    uint2 h2 = Wh2[fi], l2 = Wl2[fi];
                    uint32_t bh[2] = {h2.x, h2.y}, bl[2] = {l2.x, l2.y};
#pragma unroll
                    for (int m = 0; m < MT; m++) {
                        mma_bf16(acc[m][f], ah[m], bh);
                        mma_bf16(acc[m][f], ah[m], bl);
                        mma_bf16(acc[m][f], al[m], bh);
                    }
                }
            }
        }
    }

    const int r0 = lane >> 2, c0 = (lane & 3) * 2;
#pragma unroll
    for (int m = 0; m < MT; m++)
#pragma unroll
        for (int f = 0; f < NF; f++) {
            const int mm = mg * MT + m;
            int co = cobase + f * 8 + c0;
            int gp = by * 128 + mm * 16 + r0;
            float b0v = HAS_BIAS ? bias[co] : 0.f;
            float b1v = HAS_BIAS ? bias[co + 1] : 0.f;
            float v00 = acc[m][f][0] + b0v, v01 = acc[m][f][1] + b1v;
            float v10 = acc[m][f][2] + b0v, v11 = acc[m][f][3] + b1v;
            size_t o0 = ((size_t)n * COUT + co) * 1024 + gp;
            size_t o1 = ((size_t)n * COUT + co + 1) * 1024 + gp;
            if (ADD_RES) {
                v00 += res[o0]; v01 += res[o1];
                v10 += res[o0 + 8]; v11 += res[o1 + 8];
            }
            if (RELU_OUT) {
                v00 = fmaxf(v00, 0.f); v01 = fmaxf(v01, 0.f);
                v10 = fmaxf(v10, 0.f); v11 = fmaxf(v11, 0.f);
            }
            out[o0] = v00; out[o1] = v01;
            out[o0 + 8] = v10; out[o1 + 8] = v11;
        }
}

// ---------------- conv2 as tensor (same partition) ----------------
__global__ void __launch_bounds__(256, 2) c2m_k(
    const float* __restrict__ in,
    const __nv_bfloat16* __restrict__ whi, const __nv_bfloat16* __restrict__ wlo,
    const float* __restrict__ bias, float* __restrict__ out)
{
    constexpr int COUT = 128, CW = 4, MT = 4, NF = 4, NCOG = 16, NK = 4;
    extern __shared__ char smem[];
    const uint32_t sH = smem_u32(smem), sL = sH + WBYTES;

    const int tid = threadIdx.x, wid = tid >> 5, lane = tid & 31;
    const int by = blockIdx.x, n = blockIdx.z;
    const int mg = wid / CW, cg = wid % CW;
    const int cobase = cg * 32;
    const int cogbase = cg * 4;
    const int rowidx = ((lane >> 3) & 1) * 8 + (lane & 7);
    const int khalf = lane >> 4;
    const uint2* Wh2 = (const uint2*)whi;
    const uint2* Wl2 = (const uint2*)wlo;

    float acc[MT][NF][4];
#pragma unroll
    for (int m = 0; m < MT; m++)
#pragma unroll
        for (int f = 0; f < NF; f++)
#pragma unroll
            for (int k = 0; k < 4; k++) acc[m][f][k] = 0.f;

    for (int sg = 0; sg < 4; sg++) {
        const int sy = sg >> 1, sx = sg & 1;
        if (sg) __syncthreads();
        stage_window_s2(in, n, by, sy, sx, wid, lane, smem);
        __syncthreads();

        for (int jt = 0; jt < 4; jt++) {
            const int jy = jt >> 1, jx = jt & 1;
            const int dy = jy + 1 - sy;
            const int dx = jx + 1 - sx;
            const int cx = rowidx + dx;
            const uint32_t cx7 = (uint32_t)(cx & 7);
            const int g = sg * 4 + jt;
#pragma unroll
            for (int k16 = 0; k16 < 4; k16++) {
                const uint32_t gsw = (((uint32_t)(k16 * 2 + khalf) ^ cx7) << 4);
                uint32_t ah[MT][4], al[MT][4];
#pragma unroll
                for (int m = 0; m < MT; m++) {
                    const int mm = mg * MT + m;
                    uint32_t off = (uint32_t)((((mm >> 1) + dy) * 36 + (mm & 1) * 16 + cx) << 7) + gsw;
                    ldm4(ah[m], sH + off);
                    ldm4(al[m], sL + off);
                }
#pragma unroll
                for (int f = 0; f < NF; f++) {
                    int fi = ((g * NK + k16) * NCOG + cogbase + f) * 32 + lane;
                    uint2 h2 = Wh2[fi], l2 = Wl2[fi];
                    uint32_t bh[2] = {h2.x, h2.y}, bl[2] = {l2.x, l2.y};
#pragma unroll
                    for (int m = 0; m < MT; m++) {
                        mma_bf16(acc[m][f], ah[m], bh);
                        mma_bf16(acc[m][f], ah[m], bl);
                        mma_bf16(acc[m][f], al[m], bh);
                    }
                }
            }
        }
    }

    const int r0 = lane >> 2, c0 = (lane & 3) * 2;
#pragma unroll
    for (int m = 0; m < MT; m++)
#pragma unroll
        for (int f = 0; f < NF; f++) {
            const int mm = mg * MT + m;
            int co = cobase + f * 8 + c0;
            int gp = by * 128 + mm * 16 + r0;
            float b0v = bias[co], b1v = bias[co + 1];
            float v00 = fmaxf(acc[m][f][0] + b0v, 0.f);
            float v01 = fmaxf(acc[m][f][1] + b1v, 0.f);
            float v10 = fmaxf(acc[m][f][2] + b0v, 0.f);
            float v11 = fmaxf(acc[m][f][3] + b1v, 0.f);
            size_t o0 = ((size_t)n * COUT + co) * 1024 + gp;
            size_t o1 = ((size_t)n * COUT + co + 1) * 1024 + gp;
            out[o0] = v00; out[o1] = v01;
            out[o0 + 8] = v10; out[o1 + 8] = v11;
        }
}

// ---------------- tc1 as tensor convT (same partition) ----------------
__global__ void __launch_bounds__(256, 2) tmct_k(
    const float* __restrict__ in,
    const __nv_bfloat16* __restrict__ whi, const __nv_bfloat16* __restrict__ wlo,
    const float* __restrict__ bias, float* __restrict__ out)
{
    constexpr int CIN = 128, CW = 2, MT = 2, NF = 4, NCOG = 8, NK = 8;
    extern __shared__ char smem[];
    const uint32_t sH = smem_u32(smem), sL = sH + WBYTES;

    const int tid = threadIdx.x, wid = tid >> 5, lane = tid & 31;
    const int by = blockIdx.x, pz = blockIdx.y, n = blockIdx.z;
    const int py = pz >> 1, px = pz & 1;
    const int mg = wid / CW, cg = wid % CW;
    const int cobase = cg * 32;
    const int cogbase = cg * 4;
    const int rowidx = ((lane >> 3) & 1) * 8 + (lane & 7);
    const int khalf = lane >> 4;
    const uint2* Wh2 = (const uint2*)whi;
    const uint2* Wl2 = (const uint2*)wlo;

    float acc[MT][NF][4];
#pragma unroll
    for (int m = 0; m < MT; m++)
#pragma unroll
        for (int f = 0; f < NF; f++)
#pragma unroll
            for (int k = 0; k < 4; k++) acc[m][f][k] = 0.f;

    for (int kc = 0; kc < 2; kc++) {
        if (kc) __syncthreads();
        stage_window<CIN, true>(in, n, kc, by, wid, lane, smem);
        __syncthreads();

        for (int jt = 0; jt < 4; jt++) {
            const int jy = jt >> 1, jx = jt & 1;
            const int dy = 1 - jy + py;
            const int dx = 1 - jx + px;
            const int cx = rowidx + dx;
            const uint32_t cx7 = (uint32_t)(cx & 7);
            const int g = pz * 4 + jt;
#pragma unroll
            for (int k16 = 0; k16 < 4; k16++) {
                const int kall = kc * 4 + k16;
                const uint32_t gsw = (((uint32_t)(k16 * 2 + khalf) ^ cx7) << 4);
                uint32_t ah[MT][4], al[MT][4];
#pragma unroll
                for (int m = 0; m < MT; m++) {
                    const int mm = mg * MT + m;
                    uint32_t off = (uint32_t)((((mm >> 1) + dy) * 36 + (mm & 1) * 16 + cx) << 7) + gsw;
                    ldm4(ah[m], sH + off);
                    ldm4(al[m], sL + off);
                }
#pragma unroll
                for (int f = 0; f < NF; f++) {
                    int fi = ((g * NK + kall) * NCOG + cogbase + f) * 32 + lane;
                    uint2 h2 = Wh2[fi], l2 = Wl2[fi];
                    uint32_t bh[2] = {h2.x, h2.y}, bl[2] = {l2.x, l2.y};
#pragma unroll
                    for (int m = 0; m < MT; m++) {
                        mma_bf16(acc[m][f], ah[m], bh);
                        mma_bf16(acc[m][f], ah[m], bl);
                        mma_bf16(acc[m][f], al[m], bh);
                    }
                }
            }
        }
    }

    const int r0 = lane >> 2, c0 = (lane & 3) * 2;
#pragma unroll
    for (int m = 0; m < MT; m++)
#pragma unroll
        for (int f = 0; f < NF; f++) {
            const int mm = mg * MT + m;
            int p = mm * 16 + r0;
            int co = cobase + f * 8 + c0;
            int ga = by * 4 + (p >> 5), gb = p & 31;
            int oy = 2 * ga + py, ox = 2 * gb + px;
            float b0v = bias[co], b1v = bias[co + 1];
            float v00 = fmaxf(acc[m][f][0] + b0v, 0.f);
            float v01 = fmaxf(acc[m][f][1] + b1v, 0.f);
            float v10 = fmaxf(acc[m][f][2] + b0v, 0.f);
            float v11 = fmaxf(acc[m][f][3] + b1v, 0.f);
            size_t o00 = (((size_t)n * 64 + co) * 64 + oy) * 64 + ox;
            out[o00] = v00; out[o00 + 4096] = v01;
            out[o00 + 16] = v10; out[o00 + 4096 + 16] = v11;
        }
}

// ---------------- generic direct conv (conv1 only) ----------------
template<int CIN, int COUT, int KS, int STR, int PAD, int IH, int IW, int CO_BLK, int PX,
         bool RELU_OUT>
__global__ void __launch_bounds__(256) conv_k(
    const float* __restrict__ in, const float* __restrict__ w,
    const float* __restrict__ bias, float* __restrict__ out)
{
    constexpr int OH = (IH + 2 * PAD - KS) / STR + 1;
    constexpr int OW = (IW + 2 * PAD - KS) / STR + 1;
    constexpr int KK = KS * KS;
    constexpr int COLS = STR * (PX - 1) + KS;
    extern __shared__ float sw[];

    const int n = blockIdx.z, co0 = blockIdx.y * CO_BLK, tid = threadIdx.x;
    for (int i = tid; i < CIN * KK * CO_BLK; i += blockDim.x) {
        int co = i % CO_BLK, t = (i / CO_BLK) % KK, ci = i / (CO_BLK * KK);
        sw[i] = w[((size_t)(co0 + co) * CIN + ci) * KK + t];
    }
    __syncthreads();

    int p0 = (blockIdx.x * blockDim.x + tid) * PX;
    if (p0 >= OH * OW) return;
    int oy = p0 / OW, ox0 = p0 % OW;
    int iy0 = oy * STR - PAD, ix0 = ox0 * STR - PAD;

    bool rok[KS]; int roff[KS];
#pragma unroll
    for (int ky = 0; ky < KS; ky++) {
        int y = iy0 + ky; rok[ky] = (y >= 0) && (y < IH); roff[ky] = y * IW;
    }
    bool cok[COLS]; int coff[COLS];
#pragma unroll
    for (int cx = 0; cx < COLS; cx++) {
        int x = ix0 + cx; cok[cx] = (x >= 0) && (x < IW); coff[cx] = x;
    }

    unsigned long long acc[PX][CO_BLK / 2];
#pragma unroll
    for (int px = 0; px < PX; px++)
#pragma unroll
        for (int j = 0; j < CO_BLK / 2; j++) acc[px][j] = 0ull;

    const float* inb = in + (size_t)n * CIN * IH * IW;
    for (int ci = 0; ci < CIN; ci++) {
        const float* inc = inb + (size_t)ci * IH * IW;
        const ulonglong2* wt = (const ulonglong2*)(sw + (size_t)ci * KK * CO_BLK);
#pragma unroll
        for (int ky = 0; ky < KS; ky++) {
            unsigned long long pv[COLS];
#pragma unroll
            for (int cx = 0; cx < COLS; cx++) {
                float val = (rok[ky] && cok[cx]) ? inc[roff[ky] + coff[cx]] : 0.f;
                pv[cx] = pk2(val, val);
            }
#pragma unroll
            for (int kx = 0; kx < KS; kx++) {
                const int t = ky * KS + kx;
#pragma unroll
                for (int q = 0; q < CO_BLK / 4; q++) {
                    ulonglong2 ww = wt[t * (CO_BLK / 4) + q];
#pragma unroll
                    for (int px = 0; px < PX; px++) {
                        fma2(acc[px][2 * q + 0], pv[px * STR + kx], ww.x);
                        fma2(acc[px][2 * q + 1], pv[px * STR + kx], ww.y);
                    }
                }
            }
        }
    }

    float* ob = out + ((size_t)n * COUT + co0) * OH * OW + p0;
#pragma unroll
    for (int j = 0; j < CO_BLK / 2; j++) {
        float b0 = bias[co0 + 2 * j], b1 = bias[co0 + 2 * j + 1];
        float r0[PX], r1[PX];
#pragma unroll
        for (int px = 0; px < PX; px++) {
            float2 f = upk2(acc[px][j]);
            r0[px] = f.x + b0; r1[px] = f.y + b1;
            if (RELU_OUT) { r0[px] = fmaxf(r0[px], 0.f); r1[px] = fmaxf(r1[px], 0.f); }
        }
        float* o0 = ob + (size_t)(2 * j + 0) * OH * OW;
        float* o1 = ob + (size_t)(2 * j + 1) * OH * OW;
        if (PX == 2) {
            *(float2*)o0 = make_float2(r0[0], r0[1 % PX]);
            *(float2*)o1 = make_float2(r1[0], r1[1 % PX]);
        } else {
#pragma unroll
            for (int px = 0; px < PX; px++) { o0[px] = r0[px]; o1[px] = r1[px]; }
        }
    }
}

// ---------------- transposed conv k=4 s=2 p=1 (gather) — tc2 only ----------------
template<int CIN, int COUT, int IH, int IW, int CO_BLK, int PX,
         bool RELU_IN, bool RELU_OUT>
__global__ void __launch_bounds__(256) convt_k(
    const float* __restrict__ in, const float* __restrict__ w,
    const float* __restrict__ bias, float* __restrict__ out)
{
    constexpr int OH = IH * 2, OW = IW * 2;
    extern __shared__ float sw[];

    const int n = blockIdx.z, co0 = blockIdx.y * CO_BLK, tid = threadIdx.x;
    for (int i = tid; i < CIN * 16 * CO_BLK; i += blockDim.x) {
        int co = i % CO_BLK, t = (i / CO_BLK) % 16, ci = i / (CO_BLK * 16);
        sw[i] = (co0 + co < COUT) ? w[((size_t)ci * COUT + (co0 + co)) * 16 + t] : 0.f;
    }
    __syncthreads();

    int p0 = (blockIdx.x * blockDim.x + tid) * PX;
    if (p0 >= OH * OW) return;
    int oy = p0 / OW, ox0 = p0 % OW;
    const int kpy = (oy + 1) & 1, kp0 = (ox0 + 1) & 1;

    int iy[2]; bool vy[2];
#pragma unroll
    for (int a = 0; a < 2; a++) {
        int ky = kpy + 2 * a, yy = oy + 1 - ky;
        iy[a] = yy >> 1; vy[a] = (yy >= 0) && (iy[a] < IH);
    }
    int ixp[PX][2]; bool vxp[PX][2];
#pragma unroll
    for (int px = 0; px < PX; px++) {
        int kpx = (kp0 + px) & 1;
#pragma unroll
        for (int b = 0; b < 2; b++) {
            int kx = kpx + 2 * b, xx = ox0 + px + 1 - kx;
            ixp[px][b] = xx >> 1; vxp[px][b] = (xx >= 0) && (ixp[px][b] < IW);
        }
    }

    unsigned long long acc[PX][CO_BLK / 2];
#pragma unroll
    for (int px = 0; px < PX; px++)
#pragma unroll
        for (int j = 0; j < CO_BLK / 2; j++) acc[px][j] = 0ull;

    const float* inb = in + (size_t)n * CIN * IH * IW;
    for (int ci = 0; ci < CIN; ci++) {
        const float* inc = inb + (size_t)ci * IH * IW;
        unsigned long long pv[PX][4];
#pragma unroll
        for (int px = 0; px < PX; px++)
#pragma unroll
            for (int a = 0; a < 2; a++)
#pragma unroll
                for (int b = 0; b < 2; b++) {
                    float val = 0.f;
                    if (vy[a] && vxp[px][b]) val = inc[iy[a] * IW + ixp[px][b]];
                    if (RELU_IN) val = fmaxf(val, 0.f);
                    pv[px][a * 2 + b] = pk2(val, val);
                }
        const ulonglong2* wt = (const ulonglong2*)(sw + (size_t)ci * 16 * CO_BLK);
#pragma unroll
        for (int g = 0; g < 2; g++) {
            const int kpxg = (kp0 + g) & 1;
#pragma unroll
            for (int a = 0; a < 2; a++)
#pragma unroll
                for (int b = 0; b < 2; b++) {
                    const int t = (kpy + 2 * a) * 4 + (kpxg + 2 * b);
#pragma unroll
                    for (int q = 0; q < CO_BLK / 4; q++) {
                        ulonglong2 ww = wt[t * (CO_BLK / 4) + q];
#pragma unroll
                        for (int px = g; px < PX; px += 2) {
                            fma2(acc[px][2 * q + 0], pv[px][a * 2 + b], ww.x);
                            fma2(acc[px][2 * q + 1], pv[px][a * 2 + b], ww.y);
                        }
                    }
                }
        }
    }

    float* ob = out + ((size_t)n * COUT + co0) * OH * OW + p0;
#pragma unroll
    for (int j = 0; j < CO_BLK / 2; j++) {
        float b0 = (co0 + 2 * j < COUT) ? bias[co0 + 2 * j] : 0.f;
        float b1 = (co0 + 2 * j + 1 < COUT) ? bias[co0 + 2 * j + 1] : 0.f;
        float r0[PX], r1[PX];
#pragma unroll
        for (int px = 0; px < PX; px++) {
            float2 f = upk2(acc[px][j]);
            r0[px] = f.x + b0; r1[px] = f.y + b1;
            if (RELU_OUT) { r0[px] = fmaxf(r0[px], 0.f); r1[px] = fmaxf(r1[px], 0.f); }
        }
        float* o0 = ob + (size_t)(2 * j + 0) * OH * OW;
        float* o1 = ob + (size_t)(2 * j + 1) * OH * OW;
#pragma unroll
        for (int px = 0; px < PX; px++) {
            if (co0 + 2 * j + 0 < COUT) o0[px] = r0[px];
            if (co0 + 2 * j + 1 < COUT) o1[px] = r1[px];
        }
    }
}

// ---------------- VQ ----------------
__global__ void vq_init_k(const float* __restrict__ E, float* __restrict__ enorm,
                          float* __restrict__ counts, float* __restrict__ sqsum)
{
    int k = blockIdx.x * blockDim.x + threadIdx.x;
    if (k < KCODES) {
        float s = 0.f;
#pragma unroll
        for (int d = 0; d < DDIM; d++) { float e = E[k * DDIM + d]; s += e * e; }
        enorm[k] = s; counts[k] = 0.f;
    }
    if (k == 0) sqsum[0] = 0.f;
}

__global__ void vq_k(const float* __restrict__ ze, const float* __restrict__ E,
                     const float* __restrict__ enorm, float* __restrict__ zq,
                     float* __restrict__ counts, float* __restrict__ sqsum)
{
    __shared__ float sE[128 * DDIM];
    __shared__ float sN[128];
    __shared__ float sred[8];

    const int tid = threadIdx.x;
    const int r = blockIdx.x * blockDim.x + tid;
    const int n = r >> 10, hw = r & 1023;

    const float* zb = ze + (size_t)n * DDIM * 1024 + hw;
    float z[DDIM];
#pragma unroll
    for (int d = 0; d < DDIM; d++) z[d] = zb[(size_t)d * 1024];
    float zn = 0.f;
#pragma unroll
    for (int d = 0; d < DDIM; d++) zn += z[d] * z[d];
    unsigned long long z2[DDIM / 2];
#pragma unroll
    for (int d = 0; d < DDIM / 2; d++) z2[d] = pk2(z[2 * d], z[2 * d + 1]);

    float best = 3.4e38f; int bidx = 0;
    for (int c = 0; c < KCODES / 128; c++) {
        __syncthreads();
        for (int i = tid; i < 128 * DDIM; i += blockDim.x) sE[i] = E[c * 128 * DDIM + i];
        for (int i = tid; i < 128; i += blockDim.x) sN[i] = enorm[c * 128 + i];
        __syncthreads();
        for (int k = 0; k < 128; k++) {
            const ulonglong2* e2 = (const ulonglong2*)(sE + k * DDIM);
            unsigned long long a0 = 0ull, a1 = 0ull;
#pragma unroll
            for (int m = 0; m < DDIM / 4; m++) {
                ulonglong2 e = e2[m];
                fma2(a0, z2[2 * m + 0], e.x);
                fma2(a1, z2[2 * m + 1], e.y);
            }
            float2 f0 = upk2(a0), f1 = upk2(a1);
            float dist = zn + sN[k] - 2.f * ((f0.x + f0.y) + (f1.x + f1.y));
            if (dist < best) { best = dist; bidx = c * 128 + k; }
        }
    }

    float local = 0.f;
    const float* eb = E + (size_t)bidx * DDIM;
    float* zqb = zq + (size_t)n * DDIM * 1024 + hw;
#pragma unroll
    for (int d = 0; d < DDIM; d++) {
        float e = eb[d];
        zqb[(size_t)d * 1024] = e;
        float df = e - z[d];
        local += df * df;
    }
    atomicAdd(&counts[bidx], 1.f);
#pragma unroll
    for (int o = 16; o; o >>= 1) local += __shfl_down_sync(0xffffffffu, local, o);
    if ((tid & 31) == 0) sred[tid >> 5] = local;
    __syncthreads();
    if (tid < 8) {
        local = sred[tid];
#pragma unroll
        for (int o = 4; o; o >>= 1) local += __shfl_down_sync(0xffu, local, o);
        if (tid == 0) atomicAdd(sqsum, local);
    }
}

__global__ void finalize_k(const float* __restrict__ counts, const float* __restrict__ sqsum,
                           float* __restrict__ out)
{
    __shared__ float sred[16];
    int tid = threadIdx.x;
    float p = counts[tid] * (1.f / 65536.f);
    float term = -p * log2f(p + 1e-10f);
#pragma unroll
    for (int o = 16; o; o >>= 1) term += __shfl_down_sync(0xffffffffu, term, o);
    if ((tid & 31) == 0) sred[tid >> 5] = term;
    __syncthreads();
    if (tid < 16) {
        term = sred[tid];
#pragma unroll
        for (int o = 8; o; o >>= 1) term += __shfl_down_sync(0xffffu, term, o);
        if (tid == 0) {
            float mse = sqsum[0] / (65536.f * 64.f);
            const int base = 1 + BATCH * 3 * 128 * 128;
            out[0] = 1.25f * mse;
            out[base + 0] = mse;
            out[base + 1] = mse;
            out[base + 2] = exp2f(term);
        }
    }
}

// ---------------- launch ----------------
extern "C" void kernel_launch(void* const* d_in, const int* in_sizes, int n_in,
                              void* d_out, int out_size)
{
    const float* x        = (const float*)d_in[0];
    const float* enc_w1   = (const float*)d_in[1];
    const float* enc_b1   = (const float*)d_in[2];
    const float* enc_w2   = (const float*)d_in[3];
    const float* enc_b2   = (const float*)d_in[4];
    const float* enc_w3   = (const float*)d_in[5];
    const float* enc_b3   = (const float*)d_in[6];
    const float* enc_w4   = (const float*)d_in[7];
    const float* enc_b4   = (const float*)d_in[8];
    const float* enc_rw1  = (const float*)d_in[9];
    const float* enc_rw2  = (const float*)d_in[10];
    const float* enc_adjw = (const float*)d_in[11];
    const float* enc_adjb = (const float*)d_in[12];
    const float* E        = (const float*)d_in[13];
    const float* dec_adjw = (const float*)d_in[14];
    const float* dec_adjb = (const float*)d_in[15];
    const float* dec_rw1  = (const float*)d_in[16];
    const float* dec_rw2  = (const float*)d_in[17];
    const float* tc1_w    = (const float*)d_in[18];
    const float* tc1_b    = (const float*)d_in[19];
    const float* tc2_w    = (const float*)d_in[20];
    const float* tc2_b    = (const float*)d_in[21];

    float* out   = (float*)d_out;
    float* recon = out + 1;

    float *h1, *a, *b, *mid, *ze, *zq, *enorm, *counts, *sqsum;
    __nv_bfloat16 *whi, *wlo;
    cudaGetSymbolAddress((void**)&h1, d_h1);
    cudaGetSymbolAddress((void**)&a, d_a);
    cudaGetSymbolAddress((void**)&b, d_b);
    cudaGetSymbolAddress((void**)&mid, d_mid);
    cudaGetSymbolAddress((void**)&ze, d_ze);
    cudaGetSymbolAddress((void**)&zq, d_zq);
    cudaGetSymbolAddress((void**)&enorm, d_enorm);
    cudaGetSymbolAddress((void**)&counts, d_counts);
    cudaGetSymbolAddress((void**)&sqsum, d_sqsum);
    cudaGetSymbolAddress((void**)&whi, d_whi);
    cudaGetSymbolAddress((void**)&wlo, d_wlo);

    const size_t O_W3 = 0, O_W4 = 147456, O_R1E0 = 294912, O_R1E1 = 368640;
    const size_t O_R2E0 = 442368, O_R2E1 = 450560, O_ADJ = 458752, O_DADJ = 466944;
    const size_t O_R1D0 = 540672, O_R1D1 = 614400, O_R2D0 = 688128, O_R2D1 = 696320;
    const size_t O_TC1 = 704512, O_C2 = 835584;

    {
        static const struct { int off, size, cout, cin, kk; } segs[12] = {
            {0, 147456, 128, 128, 9}, {147456, 147456, 128, 128, 9},
            {294912, 73728, 64, 128, 9}, {368640, 73728, 64, 128, 9},
            {442368, 8192, 128, 64, 1}, {450560, 8192, 128, 64, 1},
            {458752, 8192, 64, 128, 1}, {466944, 73728, 128, 64, 9},
            {540672, 73728, 64, 128, 9}, {614400, 73728, 64, 128, 9},
            {688128, 8192, 128, 64, 1}, {696320, 8192, 128, 64, 1}};
        cudaMemcpyToSymbolAsync(c_wseg, segs, sizeof(segs), 0, cudaMemcpyHostToDevice);
    }
    WPrepArgs wa;
    wa.s[0] = enc_w3; wa.s[1] = enc_w4;
    wa.s[2] = enc_rw1; wa.s[3] = enc_rw1 + 64 * 128 * 9;
    wa.s[4] = enc_rw2; wa.s[5] = enc_rw2 + 128 * 64;
    wa.s[6] = enc_adjw; wa.s[7] = dec_adjw;
    wa.s[8] = dec_rw1; wa.s[9] = dec_rw1 + 64 * 128 * 9;
    wa.s[10] = dec_rw2; wa.s[11] = dec_rw2 + 128 * 64;
    wa.tc1 = tc1_w; wa.c2 = enc_w2;
    wprep_all_k<<<(966656 + 255) / 256, 256>>>(wa, whi, wlo);

    const int TPB = 256;
    const dim3 TG(8, 1, BATCH);

    conv_k<3, 64, 4, 2, 1, 128, 128, 16, 2, true>
        <<<dim3(4096 / (TPB * 2), 4, BATCH), TPB, 3 * 16 * 16 * 4>>>(x, enc_w1, enc_b1, h1);

    auto t3_128_relu = mconv2_k<128, 128, 3, false, true, true, false>;
    auto t3_128      = mconv2_k<128, 128, 3, false, false, true, false>;
    auto t3_r1       = mconv2_k<128, 64, 3, true, false, false, false>;
    auto t1_r2       = mconv2_k<64, 128, 1, true, false, false, true>;
    auto t1_adj      = mconv2_k<128, 64, 1, true, false, true, false>;
    auto t3_dadj     = mconv2_k<64, 128, 3, false, false, true, false>;
    cudaFuncSetAttribute((const void*)t3_128_relu, cudaFuncAttributeMaxDynamicSharedMemorySize, MC_SMEM);
    cudaFuncSetAttribute((const void*)t3_128, cudaFuncAttributeMaxDynamicSharedMemorySize, MC_SMEM);
    cudaFuncSetAttribute((const void*)t3_r1, cudaFuncAttributeMaxDynamicSharedMemorySize, MC_SMEM);
    cudaFuncSetAttribute((const void*)t1_r2, cudaFuncAttributeMaxDynamicSharedMemorySize, MC_SMEM);
    cudaFuncSetAttribute((const void*)t1_adj, cudaFuncAttributeMaxDynamicSharedMemorySize, MC_SMEM);
    cudaFuncSetAttribute((const void*)t3_dadj, cudaFuncAttributeMaxDynamicSharedMemorySize, MC_SMEM);
    cudaFuncSetAttribute((const void*)tmct_k, cudaFuncAttributeMaxDynamicSharedMemorySize, MC_SMEM);
    cudaFuncSetAttribute((const void*)c2m_k, cudaFuncAttributeMaxDynamicSharedMemorySize, MC_SMEM);

    c2m_k<<<TG, TPB, MC_SMEM>>>(h1, whi + O_C2, wlo + O_C2, enc_b2, a);

    t3_128_relu<<<TG, TPB, MC_SMEM>>>(a, whi + O_W3, wlo + O_W3, enc_b3, nullptr, b);
    t3_128<<<TG, TPB, MC_SMEM>>>(b, whi + O_W4, wlo + O_W4, enc_b4, nullptr, a);
    t3_r1<<<TG, TPB, MC_SMEM>>>(a, whi + O_R1E0, wlo + O_R1E0, nullptr, nullptr, mid);
    t1_r2<<<TG, TPB, MC_SMEM>>>(mid, whi + O_R2E0, wlo + O_R2E0, nullptr, a, a);
    t3_r1<<<TG, TPB, MC_SMEM>>>(a, whi + O_R1E1, wlo + O_R1E1, nullptr, nullptr, mid);
    t1_r2<<<TG, TPB, MC_SMEM>>>(mid, whi + O_R2E1, wlo + O_R2E1, nullptr, a, a);
    t1_adj<<<TG, TPB, MC_SMEM>>>(a, whi + O_ADJ, wlo + O_ADJ, enc_adjb, nullptr, ze);

    vq_init_k<<<2, 256>>>(E, enorm, counts, sqsum);
    vq_k<<<65536 / 256, 256>>>(ze, E, enorm, zq, counts, sqsum);

    t3_dadj<<<TG, TPB, MC_SMEM>>>(zq, whi + O_DADJ, wlo + O_DADJ, dec_adjb, nullptr, a);
    t3_r1<<<TG, TPB, MC_SMEM>>>(a, whi + O_R1D0, wlo + O_R1D0, nullptr, nullptr, mid);
    t1_r2<<<TG, TPB, MC_SMEM>>>(mid, whi + O_R2D0, wlo + O_R2D0, nullptr, a, a);
    t3_r1<<<TG, TPB, MC_SMEM>>>(a, whi + O_R1D1, wlo + O_R1D1, nullptr, nullptr, mid);
    t1_r2<<<TG, TPB, MC_SMEM>>>(mid, whi + O_R2D1, wlo + O_R2D1, nullptr, a, a);

    tmct_k<<<dim3(8, 4, BATCH), TPB, MC_SMEM>>>(a, whi + O_TC1, wlo + O_TC1, tc1_b, h1);
    convt_k<64, 3, 64, 64, 4, 4, false, false>
        <<<dim3(16384 / (TPB * 4), 1, BATCH), TPB, 64 * 16 * 4 * 4>>>(h1, tc2_w, tc2_b, recon);

    finalize_k<<<1, 512>>>(counts, sqsum, out);
}